// round 8
// baseline (speedup 1.0000x reference)
#include <cuda_runtime.h>
#include <cuda_bf16.h>
#include <cstdint>
#include <math.h>

static constexpr int DIM = 2048;
static constexpr int LD = 2048;
static constexpr float NSC_A = 3.4445f;
static constexpr float NSC_B = -4.7750f;
static constexpr float NSC_C = 2.0315f;

// ---------------- scratch (allocation-free: __device__ globals) -------------
__device__ __align__(256) float g_X[DIM * DIM];
__device__ __align__(256) __nv_bfloat16 g_Xhi [2][DIM * DIM];
__device__ __align__(256) __nv_bfloat16 g_Xlo [2][DIM * DIM];
__device__ __align__(256) __nv_bfloat16 g_XThi[2][DIM * DIM];
__device__ __align__(256) __nv_bfloat16 g_XTlo[2][DIM * DIM];
__device__ __align__(256) __nv_bfloat16 g_Ghi [DIM * DIM];
__device__ __align__(256) __nv_bfloat16 g_Glo [DIM * DIM];
__device__ __align__(256) __nv_bfloat16 g_Bhi [DIM * DIM];
__device__ __align__(256) __nv_bfloat16 g_Blo [DIM * DIM];
__device__ __align__(256) __nv_bfloat16 g_xbig_hi[16384 * DIM];
__device__ __align__(256) __nv_bfloat16 g_xbig_lo[16384 * DIM];
__device__ float g_partial[256];
__device__ float g_scale;

// ---------------- helpers ----------------------------------------------------
__device__ __forceinline__ uint32_t smem_u32(const void* p) {
    uint32_t a;
    asm("{ .reg .u64 t; cvta.to.shared.u64 t, %1; cvt.u32.u64 %0, t; }" : "=r"(a) : "l"(p));
    return a;
}
__device__ __forceinline__ void cpa16(uint32_t dst, const void* src) {
    asm volatile("cp.async.cg.shared.global [%0], [%1], 16;" :: "r"(dst), "l"(src) : "memory");
}
#define CP_COMMIT() asm volatile("cp.async.commit_group;" ::: "memory")
#define CP_WAIT1()  asm volatile("cp.async.wait_group 1;" ::: "memory")
#define CP_WAIT0()  asm volatile("cp.async.wait_group 0;" ::: "memory")

#define LDMX4(r, a)                                                              \
    asm volatile("ldmatrix.sync.aligned.m8n8.x4.shared.b16 {%0,%1,%2,%3}, [%4];" \
        : "=r"((r)[0]), "=r"((r)[1]), "=r"((r)[2]), "=r"((r)[3]) : "r"(a))

#define MMA16816(acc, a, b0, b1)                                                  \
    asm volatile("mma.sync.aligned.m16n8k16.row.col.f32.bf16.bf16.f32 "           \
        "{%0,%1,%2,%3}, {%4,%5,%6,%7}, {%8,%9}, {%0,%1,%2,%3};"                   \
        : "+f"((acc)[0]), "+f"((acc)[1]), "+f"((acc)[2]), "+f"((acc)[3])          \
        : "r"((a)[0]), "r"((a)[1]), "r"((a)[2]), "r"((a)[3]), "r"(b0), "r"(b1))

__device__ __forceinline__ void store_split4(__nv_bfloat16* H, __nv_bfloat16* L, size_t off,
                                             float f0, float f1, float f2, float f3) {
    __nv_bfloat16 h0 = __float2bfloat16(f0), h1 = __float2bfloat16(f1);
    __nv_bfloat16 h2 = __float2bfloat16(f2), h3 = __float2bfloat16(f3);
    __nv_bfloat162 hA, hB, lA, lB;
    hA.x = h0; hA.y = h1; hB.x = h2; hB.y = h3;
    lA.x = __float2bfloat16(f0 - __bfloat162float(h0));
    lA.y = __float2bfloat16(f1 - __bfloat162float(h1));
    lB.x = __float2bfloat16(f2 - __bfloat162float(h2));
    lB.y = __float2bfloat16(f3 - __bfloat162float(h3));
    *(__nv_bfloat162*)(H + off) = hA;
    *(__nv_bfloat162*)(H + off + 2) = hB;
    *(__nv_bfloat162*)(L + off) = lA;
    *(__nv_bfloat162*)(L + off + 2) = lB;
}
__device__ __forceinline__ void store_split2(__nv_bfloat16* H, __nv_bfloat16* L, size_t off,
                                             float f0, float f1) {
    __nv_bfloat16 h0 = __float2bfloat16(f0), h1 = __float2bfloat16(f1);
    __nv_bfloat162 h2, l2;
    h2.x = h0; h2.y = h1;
    l2.x = __float2bfloat16(f0 - __bfloat162float(h0));
    l2.y = __float2bfloat16(f1 - __bfloat162float(h1));
    *(__nv_bfloat162*)(H + off) = h2;
    *(__nv_bfloat162*)(L + off) = l2;
}

// ---------------- small kernels ---------------------------------------------
__global__ void norm_partial_kernel(const float* __restrict__ w, int n) {
    __shared__ float sd[256];
    float s = 0.f;
    for (int i = blockIdx.x * blockDim.x + threadIdx.x; i < n; i += gridDim.x * blockDim.x) {
        float v = w[i];
        s = fmaf(v, v, s);
    }
    sd[threadIdx.x] = s;
    __syncthreads();
    for (int o = 128; o; o >>= 1) {
        if (threadIdx.x < o) sd[threadIdx.x] += sd[threadIdx.x + o];
        __syncthreads();
    }
    if (threadIdx.x == 0) g_partial[blockIdx.x] = sd[0];
}
__global__ void norm_finalize_kernel() {
    __shared__ float sd[256];
    sd[threadIdx.x] = g_partial[threadIdx.x];
    __syncthreads();
    for (int o = 128; o; o >>= 1) {
        if (threadIdx.x < o) sd[threadIdx.x] += sd[threadIdx.x + o];
        __syncthreads();
    }
    if (threadIdx.x == 0) g_scale = 1.0f / (sqrtf(sd[0]) + 1e-7f);
}
__global__ void scale_split_kernel(const float* __restrict__ w, float* __restrict__ X,
                                   __nv_bfloat16* __restrict__ hi, __nv_bfloat16* __restrict__ lo,
                                   int n) {
    const float s = g_scale;
    for (int i = blockIdx.x * blockDim.x + threadIdx.x; i < n; i += gridDim.x * blockDim.x) {
        float v = w[i] * s;
        X[i] = v;
        __nv_bfloat16 h = __float2bfloat16(v);
        hi[i] = h;
        lo[i] = __float2bfloat16(v - __bfloat162float(h));
    }
}
__global__ void split_kernel(const float* __restrict__ s, __nv_bfloat16* __restrict__ hi,
                             __nv_bfloat16* __restrict__ lo, int n) {
    for (int i = blockIdx.x * blockDim.x + threadIdx.x; i < n; i += gridDim.x * blockDim.x) {
        float v = s[i];
        __nv_bfloat16 h = __float2bfloat16(v);
        hi[i] = h;
        lo[i] = __float2bfloat16(v - __bfloat162float(h));
    }
}
__global__ void strans_kernel(const float* __restrict__ src,
                              __nv_bfloat16* __restrict__ dhi, __nv_bfloat16* __restrict__ dlo) {
    __shared__ float t[32][33];
    int x = blockIdx.x * 32 + threadIdx.x;
    int y0 = blockIdx.y * 32;
    for (int j = threadIdx.y; j < 32; j += 8)
        t[j][threadIdx.x] = src[(size_t)(y0 + j) * LD + x];
    __syncthreads();
    int ox = blockIdx.y * 32 + threadIdx.x;
    for (int j = threadIdx.y; j < 32; j += 8) {
        float v = t[threadIdx.x][j];
        size_t o = (size_t)(blockIdx.x * 32 + j) * LD + ox;
        __nv_bfloat16 h = __float2bfloat16(v);
        dhi[o] = h;
        dlo[o] = __float2bfloat16(v - __bfloat162float(h));
    }
}

// ====== TRIANGULAR kernel v3 (modes 0/1): 8 warps, split-K, 64x64 tiles ======
// Warps 0-3 (k-group 0) handle even chunks, warps 4-7 odd chunks; each group
// is a 2x2 grid of 64x64 warp tiles. Partials reduced through the fp32 stage.
static constexpr int BTK = 32;
static constexpr int NCT = DIM / BTK;          // 64 chunks
static constexpr int TPITCH = 80;              // 64B data + 16B pad
static constexpr int AT_B = 128 * TPITCH;      // 10240
static constexpr int STG_T = 4 * AT_B;         // 40960
static constexpr int NSTG_T = 3;
static constexpr int SMEM_TRI = NSTG_T * STG_T;  // 122880

template <int MODE>
__global__ __launch_bounds__(256, 1) void mmagemm_tri(
    const __nv_bfloat16* __restrict__ Ahi, const __nv_bfloat16* __restrict__ Alo,
    const __nv_bfloat16* __restrict__ Bhi, const __nv_bfloat16* __restrict__ Blo,
    const __nv_bfloat16* __restrict__ auxhi, const __nv_bfloat16* __restrict__ auxlo,
    __nv_bfloat16* __restrict__ Chi, __nv_bfloat16* __restrict__ Clo) {
    extern __shared__ char sm[];
    const uint32_t smb = smem_u32(sm);
    const int tid = threadIdx.x;
    const int wid = tid >> 5;
    const int lane = tid & 31;
    const int kg = wid >> 2;          // k-group 0/1
    const int wig = wid & 3;          // warp-in-group

    const int i = blockIdx.x;
    float fq = sqrtf(8.0f * (float)i + 1.0f);
    int tn = (int)((fq - 1.0f) * 0.5f);
    while ((tn + 1) * (tn + 2) / 2 <= i) tn++;
    while (tn * (tn + 1) / 2 > i) tn--;
    int tm = i - tn * (tn + 1) / 2;
    const int bM = tm * 128;
    const int bN = tn * 128;

    // loader: 256 rows (A 128 + B 128) x 4 q of 16B, hi+lo
    auto load_chunk = [&](int c, int s) {
        const uint32_t st = smb + s * STG_T;
#pragma unroll
        for (int it = 0; it < 4; it++) {
            const int idx = tid + it * 256;   // 0..1023
            const int row = idx >> 2;         // 0..255
            const int q = idx & 3;
            if (row < 128) {
                const size_t g = (size_t)(bM + row) * LD + c * BTK + q * 8;
                const uint32_t so = st + row * TPITCH + q * 16;
                cpa16(so, Ahi + g);
                cpa16(so + AT_B, Alo + g);
            } else {
                const int br = row - 128;
                const size_t g = (size_t)(bN + br) * LD + c * BTK + q * 8;
                const uint32_t so = st + 2 * AT_B + br * TPITCH + q * 16;
                cpa16(so, Bhi + g);
                cpa16(so + AT_B, Blo + g);
            }
        }
    };

    // within group: 2x2 warp grid; warp tile 64x64
    const int wm = wig & 1;
    const int wn = wig >> 1;
    const int arowL = wm * 64 + (lane & 15);
    const int aChunk = lane >> 4;
    const int browL = wn * 64 + (lane & 7) + ((lane >> 4) & 1) * 8;
    const int bChunk = (lane >> 3) & 1;

    float acc[4][8][4];
#pragma unroll
    for (int a = 0; a < 4; a++)
#pragma unroll
        for (int b = 0; b < 8; b++)
#pragma unroll
            for (int q = 0; q < 4; q++) acc[a][b][q] = 0.f;

    load_chunk(0, 0);
    CP_COMMIT();
    load_chunk(1, 1);
    CP_COMMIT();

#pragma unroll 1
    for (int c = 0; c < NCT; c++) {
        if (c + 1 < NCT) CP_WAIT1(); else CP_WAIT0();
        __syncthreads();
        if (c + 2 < NCT) { load_chunk(c + 2, (c + 2) % NSTG_T); CP_COMMIT(); }

        if ((c & 1) == kg) {   // this k-group's chunk
            const uint32_t st = smb + (c % NSTG_T) * STG_T;
#pragma unroll
            for (int kk = 0; kk < 2; kk++) {
                uint32_t ah[4][4], al[4][4];
#pragma unroll
                for (int mt = 0; mt < 4; mt++) {
                    const uint32_t addr = st + (uint32_t)(arowL + mt * 16) * TPITCH +
                                          (uint32_t)(kk * 2 + aChunk) * 16;
                    LDMX4(ah[mt], addr);
                    LDMX4(al[mt], addr + AT_B);
                }
                uint32_t bh[4][4], bl[4][4];
#pragma unroll
                for (int nt = 0; nt < 4; nt++) {
                    const uint32_t addr = st + 2 * AT_B +
                                          (uint32_t)(browL + nt * 16) * TPITCH +
                                          (uint32_t)(kk * 2 + bChunk) * 16;
                    LDMX4(bh[nt], addr);
                    LDMX4(bl[nt], addr + AT_B);
                }
#pragma unroll
                for (int mt = 0; mt < 4; mt++)
#pragma unroll
                    for (int nt = 0; nt < 4; nt++) {
                        MMA16816(acc[mt][2 * nt],     ah[mt], bh[nt][0], bh[nt][1]);
                        MMA16816(acc[mt][2 * nt],     ah[mt], bl[nt][0], bl[nt][1]);
                        MMA16816(acc[mt][2 * nt],     al[mt], bh[nt][0], bh[nt][1]);
                        MMA16816(acc[mt][2 * nt + 1], ah[mt], bh[nt][2], bh[nt][3]);
                        MMA16816(acc[mt][2 * nt + 1], ah[mt], bl[nt][2], bl[nt][3]);
                        MMA16816(acc[mt][2 * nt + 1], al[mt], bh[nt][2], bh[nt][3]);
                    }
            }
        }
    }

    // ---- reduce partials through fp32 stage (64 KB), swizzle col^(row&31) ---
    const int qrow = lane >> 2;
    const int qcol = (lane & 3) * 2;
    float* stage = (float*)sm;
    __syncthreads();
    // pass 1: k-group 0 writes raw partials
    if (kg == 0) {
#pragma unroll
        for (int mt = 0; mt < 4; mt++)
#pragma unroll
            for (int h = 0; h < 2; h++) {
                const int rl = wm * 64 + mt * 16 + qrow + h * 8;
#pragma unroll
                for (int n8 = 0; n8 < 8; n8++) {
                    const int cl = wn * 64 + n8 * 8 + qcol;
                    stage[rl * 128 + (cl ^ (rl & 31))] = acc[mt][n8][h * 2 + 0];
                    stage[rl * 128 + ((cl + 1) ^ (rl & 31))] = acc[mt][n8][h * 2 + 1];
                }
            }
    }
    __syncthreads();
    // pass 2: k-group 1 adds partials and applies MODE-1 coefficients
    if (kg == 1) {
#pragma unroll
        for (int mt = 0; mt < 4; mt++)
#pragma unroll
            for (int h = 0; h < 2; h++) {
                const int rl = wm * 64 + mt * 16 + qrow + h * 8;
#pragma unroll
                for (int n8 = 0; n8 < 8; n8++) {
                    const int cl = wn * 64 + n8 * 8 + qcol;
                    const int s0 = rl * 128 + (cl ^ (rl & 31));
                    const int s1 = rl * 128 + ((cl + 1) ^ (rl & 31));
                    float v0 = stage[s0] + acc[mt][n8][h * 2 + 0];
                    float v1 = stage[s1] + acc[mt][n8][h * 2 + 1];
                    if (MODE == 1) {
                        const size_t ao = (size_t)(bM + rl) * LD + bN + cl;
                        __nv_bfloat162 a2 = *(const __nv_bfloat162*)(auxhi + ao);
                        __nv_bfloat162 l2 = *(const __nv_bfloat162*)(auxlo + ao);
                        v0 = NSC_C * v0 + NSC_B * (__bfloat162float(a2.x) + __bfloat162float(l2.x));
                        v1 = NSC_C * v1 + NSC_B * (__bfloat162float(a2.y) + __bfloat162float(l2.y));
                    }
                    stage[s0] = v0;
                    stage[s1] = v1;
                }
            }
    }
    __syncthreads();

    const int c4 = lane * 4;
    // normal orientation: warp w rows w*16..+15
#pragma unroll 4
    for (int rr = 0; rr < 16; rr++) {
        const int r = wid * 16 + rr;
        const int rx = r & 31;
        float f0 = stage[r * 128 + ((c4 + 0) ^ rx)];
        float f1 = stage[r * 128 + ((c4 + 1) ^ rx)];
        float f2 = stage[r * 128 + ((c4 + 2) ^ rx)];
        float f3 = stage[r * 128 + ((c4 + 3) ^ rx)];
        store_split4(Chi, Clo, (size_t)(bM + r) * LD + bN + c4, f0, f1, f2, f3);
    }
    if (tm != tn) {
#pragma unroll 4
        for (int rr = 0; rr < 16; rr++) {
            const int r = wid * 16 + rr;
            float f0 = stage[(c4 + 0) * 128 + (r ^ ((c4 + 0) & 31))];
            float f1 = stage[(c4 + 1) * 128 + (r ^ ((c4 + 1) & 31))];
            float f2 = stage[(c4 + 2) * 128 + (r ^ ((c4 + 2) & 31))];
            float f3 = stage[(c4 + 3) * 128 + (r ^ ((c4 + 3) & 31))];
            store_split4(Chi, Clo, (size_t)(bN + r) * LD + bM + c4, f0, f1, f2, f3);
        }
    }
}

// ============ BIG kernel (modes 2/3): CTA 128x256, warp tile 64x64 ===========
static constexpr int B2M = 128, B2N = 256, B2K = 32;
static constexpr int NC2 = DIM / B2K;                    // 64 chunks
static constexpr int PITCH = 80;
static constexpr int A2_B = B2M * PITCH;                 // 10240
static constexpr int B2_B = B2N * PITCH;                 // 20480
static constexpr int STG2 = 2 * A2_B + 2 * B2_B;         // 61440
static constexpr int NSTG2 = 3;
static constexpr int SMEM_BIG = NSTG2 * STG2;            // 184320

template <int MODE>
__global__ __launch_bounds__(256, 1) void mmagemm_big(
    const __nv_bfloat16* __restrict__ Ahi, const __nv_bfloat16* __restrict__ Alo,
    const __nv_bfloat16* __restrict__ Bhi, const __nv_bfloat16* __restrict__ Blo,
    const __nv_bfloat16* __restrict__ auxhi, const __nv_bfloat16* __restrict__ auxlo,
    const float* __restrict__ bias,
    __nv_bfloat16* __restrict__ Chi, __nv_bfloat16* __restrict__ Clo,
    __nv_bfloat16* __restrict__ Thi, __nv_bfloat16* __restrict__ Tlo,
    float* __restrict__ Cf32) {
    extern __shared__ char sm[];
    const uint32_t smb = smem_u32(sm);
    const int tid = threadIdx.x;
    const int wid = tid >> 5;
    const int lane = tid & 31;
    const int bM = blockIdx.y * B2M;
    const int bN = blockIdx.x * B2N;

    auto load_chunk = [&](int c, int s) {
        const uint32_t st = smb + s * STG2;
#pragma unroll
        for (int it = 0; it < 6; it++) {
            const int i = tid + it * 256;
            const int row = i >> 2;
            const int q = i & 3;
            if (row < B2M) {
                const size_t g = (size_t)(bM + row) * LD + c * B2K + q * 8;
                const uint32_t so = st + row * PITCH + q * 16;
                cpa16(so, Ahi + g);
                cpa16(so + A2_B, Alo + g);
            } else {
                const int br = row - B2M;
                const size_t g = (size_t)(bN + br) * LD + c * B2K + q * 8;
                const uint32_t so = st + 2 * A2_B + br * PITCH + q * 16;
                cpa16(so, Bhi + g);
                cpa16(so + B2_B, Blo + g);
            }
        }
    };

    const int wm = wid & 1;
    const int wn = wid >> 1;
    const int arowL = wm * 64 + (lane & 15);
    const int aChunk = lane >> 4;
    const int browL = wn * 64 + (lane & 7) + ((lane >> 4) & 1) * 8;
    const int bChunk = (lane >> 3) & 1;

    float acc[4][8][4];
#pragma unroll
    for (int a = 0; a < 4; a++)
#pragma unroll
        for (int b = 0; b < 8; b++)
#pragma unroll
            for (int q = 0; q < 4; q++) acc[a][b][q] = 0.f;

    load_chunk(0, 0);
    CP_COMMIT();
    load_chunk(1, 1);
    CP_COMMIT();

#pragma unroll 1
    for (int c = 0; c < NC2; c++) {
        if (c + 1 < NC2) CP_WAIT1(); else CP_WAIT0();
        __syncthreads();
        if (c + 2 < NC2) { load_chunk(c + 2, (c + 2) % NSTG2); CP_COMMIT(); }

        const uint32_t st = smb + (c % NSTG2) * STG2;
#pragma unroll
        for (int kk = 0; kk < 2; kk++) {
            uint32_t ah[4][4], al[4][4];
#pragma unroll
            for (int mt = 0; mt < 4; mt++) {
                const uint32_t addr = st + (uint32_t)(arowL + mt * 16) * PITCH +
                                      (uint32_t)(kk * 2 + aChunk) * 16;
                LDMX4(ah[mt], addr);
                LDMX4(al[mt], addr + A2_B);
            }
            uint32_t bh[4][4], bl[4][4];
#pragma unroll
            for (int nt = 0; nt < 4; nt++) {
                const uint32_t addr = st + 2 * A2_B +
                                      (uint32_t)(browL + nt * 16) * PITCH +
                                      (uint32_t)(kk * 2 + bChunk) * 16;
                LDMX4(bh[nt], addr);
                LDMX4(bl[nt], addr + B2_B);
            }
#pragma unroll
            for (int mt = 0; mt < 4; mt++)
#pragma unroll
                for (int nt = 0; nt < 4; nt++) {
                    MMA16816(acc[mt][2 * nt],     ah[mt], bh[nt][0], bh[nt][1]);
                    MMA16816(acc[mt][2 * nt],     ah[mt], bl[nt][0], bl[nt][1]);
                    MMA16816(acc[mt][2 * nt],     al[mt], bh[nt][0], bh[nt][1]);
                    MMA16816(acc[mt][2 * nt + 1], ah[mt], bh[nt][2], bh[nt][3]);
                    MMA16816(acc[mt][2 * nt + 1], ah[mt], bl[nt][2], bl[nt][3]);
                    MMA16816(acc[mt][2 * nt + 1], al[mt], bh[nt][2], bh[nt][3]);
                }
        }
    }

    const int qrow = lane >> 2;
    const int qcol = (lane & 3) * 2;

    if (MODE == 3) {
#pragma unroll
        for (int mt = 0; mt < 4; mt++) {
#pragma unroll
            for (int h = 0; h < 2; h++) {
                const int row = bM + wm * 64 + mt * 16 + qrow + h * 8;
                float* cr = Cf32 + (size_t)row * LD;
#pragma unroll
                for (int n8 = 0; n8 < 8; n8++) {
                    const int col = bN + wn * 64 + n8 * 8 + qcol;
                    float2 b2 = *(const float2*)(bias + col);
                    float2 o;
                    o.x = acc[mt][n8][h * 2 + 0] + b2.x;
                    o.y = acc[mt][n8][h * 2 + 1] + b2.y;
                    *(float2*)(cr + col) = o;
                }
            }
        }
        return;
    }

    // MODE 2: stage 128x256 fp32 (128 KB), swizzle col ^ (row & 31)
    float* stage = (float*)sm;
    __syncthreads();
#pragma unroll
    for (int mt = 0; mt < 4; mt++) {
#pragma unroll
        for (int h = 0; h < 2; h++) {
            const int rl = wm * 64 + mt * 16 + qrow + h * 8;
#pragma unroll
            for (int n8 = 0; n8 < 8; n8++) {
                const int cl = wn * 64 + n8 * 8 + qcol;
                float v0 = acc[mt][n8][h * 2 + 0];
                float v1 = acc[mt][n8][h * 2 + 1];
                const size_t ao = (size_t)(bM + rl) * LD + bN + cl;
                __nv_bfloat162 a2 = *(const __nv_bfloat162*)(auxhi + ao);
                __nv_bfloat162 l2 = *(const __nv_bfloat162*)(auxlo + ao);
                v0 = fmaf(NSC_A, __bfloat162float(a2.x) + __bfloat162float(l2.x), v0);
                v1 = fmaf(NSC_A, __bfloat162float(a2.y) + __bfloat162float(l2.y), v1);
                stage[rl * 256 + (cl ^ (rl & 31))] = v0;
                stage[rl * 256 + ((cl + 1) ^ (rl & 31))] = v1;
            }
        }
    }
    __syncthreads();

    {
        const int cb = lane * 2;
#pragma unroll 2
        for (int rr = 0; rr < 16; rr++) {
            const int r = wid * 16 + rr;
            const int rx = r & 31;
#pragma unroll
            for (int j = 0; j < 4; j++) {
                const int c = cb + 64 * j;
                float f0 = stage[r * 256 + (c ^ rx)];
                float f1 = stage[r * 256 + ((c + 1) ^ rx)];
                store_split2(Chi, Clo, (size_t)(bM + r) * LD + bN + c, f0, f1);
            }
        }
    }
    {
        const int cb = lane * 2;
#pragma unroll 2
        for (int rr = 0; rr < 32; rr++) {
            const int rp = wid * 32 + rr;
#pragma unroll
            for (int j = 0; j < 2; j++) {
                const int cp = cb + 64 * j;
                float f0 = stage[cp * 256 + (rp ^ (cp & 31))];
                float f1 = stage[(cp + 1) * 256 + (rp ^ ((cp + 1) & 31))];
                store_split2(Thi, Tlo, (size_t)(bN + rp) * LD + bM + cp, f0, f1);
            }
        }
    }
}

// ---------------- launch -----------------------------------------------------
extern "C" void kernel_launch(void* const* d_in, const int* in_sizes, int n_in,
                              void* d_out, int out_size) {
    const float* x = nullptr;
    const float* w = nullptr;
    const float* bias = nullptr;
    int x_size = 0;
    for (int i = 0; i < n_in; i++) {
        const int sz = in_sizes[i];
        if (sz == DIM) bias = (const float*)d_in[i];
        else if (sz == DIM * DIM) w = (const float*)d_in[i];
        else { x = (const float*)d_in[i]; x_size = sz; }
    }
    const int B_rows = x_size / DIM;  // 16384
    float* out = (float*)d_out;

    float* pX;
    __nv_bfloat16 *pXhi[2], *pXlo[2], *pXThi[2], *pXTlo[2];
    __nv_bfloat16 *pGhi, *pGlo, *pBhi, *pBlo, *pxh, *pxl;
    cudaGetSymbolAddress((void**)&pX, g_X);
    {
        __nv_bfloat16* base;
        cudaGetSymbolAddress((void**)&base, g_Xhi);
        pXhi[0] = base; pXhi[1] = base + DIM * DIM;
        cudaGetSymbolAddress((void**)&base, g_Xlo);
        pXlo[0] = base; pXlo[1] = base + DIM * DIM;
        cudaGetSymbolAddress((void**)&base, g_XThi);
        pXThi[0] = base; pXThi[1] = base + DIM * DIM;
        cudaGetSymbolAddress((void**)&base, g_XTlo);
        pXTlo[0] = base; pXTlo[1] = base + DIM * DIM;
    }
    cudaGetSymbolAddress((void**)&pGhi, g_Ghi);
    cudaGetSymbolAddress((void**)&pGlo, g_Glo);
    cudaGetSymbolAddress((void**)&pBhi, g_Bhi);
    cudaGetSymbolAddress((void**)&pBlo, g_Blo);
    cudaGetSymbolAddress((void**)&pxh, g_xbig_hi);
    cudaGetSymbolAddress((void**)&pxl, g_xbig_lo);

    cudaFuncSetAttribute(mmagemm_tri<0>, cudaFuncAttributeMaxDynamicSharedMemorySize, SMEM_TRI);
    cudaFuncSetAttribute(mmagemm_tri<1>, cudaFuncAttributeMaxDynamicSharedMemorySize, SMEM_TRI);
    cudaFuncSetAttribute(mmagemm_big<2>, cudaFuncAttributeMaxDynamicSharedMemorySize, SMEM_BIG);
    cudaFuncSetAttribute(mmagemm_big<3>, cudaFuncAttributeMaxDynamicSharedMemorySize, SMEM_BIG);

    const int n = DIM * DIM;
    norm_partial_kernel<<<256, 256>>>(w, n);
    norm_finalize_kernel<<<1, 256>>>();
    scale_split_kernel<<<1024, 256>>>(w, pX, pXhi[0], pXlo[0], n);
    strans_kernel<<<dim3(64, 64), dim3(32, 8)>>>(pX, pXThi[0], pXTlo[0]);
    split_kernel<<<8192, 256>>>(x, pxh, pxl, B_rows * DIM);

    const int NT = 16;
    dim3 gtri(NT * (NT + 1) / 2, 1);         // 136 CTAs
    dim3 g2(DIM / B2N, DIM / B2M);           // (8, 16) = 128 CTAs
    for (int s = 0; s < 10; s++) {
        const int c0 = s & 1, n1 = c0 ^ 1;
        // G = X @ X^T (symmetric, triangular + mirror)
        mmagemm_tri<0><<<gtri, 256, SMEM_TRI>>>(
            pXhi[c0], pXlo[c0], pXhi[c0], pXlo[c0],
            nullptr, nullptr, pGhi, pGlo);
        // Bm = c*(G@G) + b*G (symmetric, triangular + mirror)
        mmagemm_tri<1><<<gtri, 256, SMEM_TRI>>>(
            pGhi, pGlo, pGhi, pGlo,
            pGhi, pGlo, pBhi, pBlo);
        // X' = Bm@X + a*X ; writes X'[n1] split + X'^T[n1] split
        mmagemm_big<2><<<g2, 256, SMEM_BIG>>>(
            pBhi, pBlo, pXThi[c0], pXTlo[c0],
            pXhi[c0], pXlo[c0], nullptr,
            pXhi[n1], pXlo[n1], pXThi[n1], pXTlo[n1], nullptr);
    }
    // out = x @ Xfinal + bias
    dim3 gout(DIM / B2N, B_rows / B2M);  // (8, 128)
    mmagemm_big<3><<<gout, 256, SMEM_BIG>>>(
        pxh, pxl, pXThi[0], pXTlo[0],
        nullptr, nullptr, bias, nullptr, nullptr, nullptr, nullptr, out);
}

// round 9
// speedup vs baseline: 1.0769x; 1.0769x over previous
#include <cuda_runtime.h>
#include <cuda_bf16.h>
#include <cstdint>
#include <math.h>

static constexpr int DIM = 2048;
static constexpr int LD = 2048;
static constexpr float NSC_A = 3.4445f;
static constexpr float NSC_B = -4.7750f;
static constexpr float NSC_C = 2.0315f;

// ---------------- scratch (allocation-free: __device__ globals) -------------
__device__ __align__(256) __nv_bfloat16 g_Xhi [2][DIM * DIM];
__device__ __align__(256) __nv_bfloat16 g_Xlo [2][DIM * DIM];
__device__ __align__(256) __nv_bfloat16 g_XThi[2][DIM * DIM];
__device__ __align__(256) __nv_bfloat16 g_XTlo[2][DIM * DIM];
__device__ __align__(256) __nv_bfloat16 g_Ghi [DIM * DIM];
__device__ __align__(256) __nv_bfloat16 g_Glo [DIM * DIM];
__device__ __align__(256) __nv_bfloat16 g_Bhi [DIM * DIM];
__device__ __align__(256) __nv_bfloat16 g_Blo [DIM * DIM];
__device__ __align__(256) __nv_bfloat16 g_xbig_hi[16384 * DIM];
__device__ __align__(256) __nv_bfloat16 g_xbig_lo[16384 * DIM];
__device__ float g_partial[256];
__device__ float g_scale;

// ---------------- helpers ----------------------------------------------------
__device__ __forceinline__ uint32_t smem_u32(const void* p) {
    uint32_t a;
    asm("{ .reg .u64 t; cvta.to.shared.u64 t, %1; cvt.u32.u64 %0, t; }" : "=r"(a) : "l"(p));
    return a;
}
__device__ __forceinline__ void cpa16(uint32_t dst, const void* src) {
    asm volatile("cp.async.cg.shared.global [%0], [%1], 16;" :: "r"(dst), "l"(src) : "memory");
}
#define CP_COMMIT() asm volatile("cp.async.commit_group;" ::: "memory")
#define CP_WAIT1()  asm volatile("cp.async.wait_group 1;" ::: "memory")
#define CP_WAIT0()  asm volatile("cp.async.wait_group 0;" ::: "memory")

#define LDMX4(r, a)                                                              \
    asm volatile("ldmatrix.sync.aligned.m8n8.x4.shared.b16 {%0,%1,%2,%3}, [%4];" \
        : "=r"((r)[0]), "=r"((r)[1]), "=r"((r)[2]), "=r"((r)[3]) : "r"(a))

#define MMA16816(acc, a, b0, b1)                                                  \
    asm volatile("mma.sync.aligned.m16n8k16.row.col.f32.bf16.bf16.f32 "           \
        "{%0,%1,%2,%3}, {%4,%5,%6,%7}, {%8,%9}, {%0,%1,%2,%3};"                   \
        : "+f"((acc)[0]), "+f"((acc)[1]), "+f"((acc)[2]), "+f"((acc)[3])          \
        : "r"((a)[0]), "r"((a)[1]), "r"((a)[2]), "r"((a)[3]), "r"(b0), "r"(b1))

__device__ __forceinline__ void store_split4(__nv_bfloat16* H, __nv_bfloat16* L, size_t off,
                                             float f0, float f1, float f2, float f3) {
    __nv_bfloat16 h0 = __float2bfloat16(f0), h1 = __float2bfloat16(f1);
    __nv_bfloat16 h2 = __float2bfloat16(f2), h3 = __float2bfloat16(f3);
    __nv_bfloat162 hA, hB, lA, lB;
    hA.x = h0; hA.y = h1; hB.x = h2; hB.y = h3;
    lA.x = __float2bfloat16(f0 - __bfloat162float(h0));
    lA.y = __float2bfloat16(f1 - __bfloat162float(h1));
    lB.x = __float2bfloat16(f2 - __bfloat162float(h2));
    lB.y = __float2bfloat16(f3 - __bfloat162float(h3));
    *(__nv_bfloat162*)(H + off) = hA;
    *(__nv_bfloat162*)(H + off + 2) = hB;
    *(__nv_bfloat162*)(L + off) = lA;
    *(__nv_bfloat162*)(L + off + 2) = lB;
}
__device__ __forceinline__ void store_split2(__nv_bfloat16* H, __nv_bfloat16* L, size_t off,
                                             float f0, float f1) {
    __nv_bfloat16 h0 = __float2bfloat16(f0), h1 = __float2bfloat16(f1);
    __nv_bfloat162 h2, l2;
    h2.x = h0; h2.y = h1;
    l2.x = __float2bfloat16(f0 - __bfloat162float(h0));
    l2.y = __float2bfloat16(f1 - __bfloat162float(h1));
    *(__nv_bfloat162*)(H + off) = h2;
    *(__nv_bfloat162*)(L + off) = l2;
}

// ---------------- small kernels ---------------------------------------------
__global__ void norm_partial_kernel(const float* __restrict__ w, int n) {
    __shared__ float sd[256];
    float s = 0.f;
    for (int i = blockIdx.x * blockDim.x + threadIdx.x; i < n; i += gridDim.x * blockDim.x) {
        float v = w[i];
        s = fmaf(v, v, s);
    }
    sd[threadIdx.x] = s;
    __syncthreads();
    for (int o = 128; o; o >>= 1) {
        if (threadIdx.x < o) sd[threadIdx.x] += sd[threadIdx.x + o];
        __syncthreads();
    }
    if (threadIdx.x == 0) g_partial[blockIdx.x] = sd[0];
}
__global__ void norm_finalize_kernel() {
    __shared__ float sd[256];
    sd[threadIdx.x] = g_partial[threadIdx.x];
    __syncthreads();
    for (int o = 128; o; o >>= 1) {
        if (threadIdx.x < o) sd[threadIdx.x] += sd[threadIdx.x + o];
        __syncthreads();
    }
    if (threadIdx.x == 0) g_scale = 1.0f / (sqrtf(sd[0]) + 1e-7f);
}
__global__ void split_kernel(const float* __restrict__ s, __nv_bfloat16* __restrict__ hi,
                             __nv_bfloat16* __restrict__ lo, int n) {
    for (int i = blockIdx.x * blockDim.x + threadIdx.x; i < n; i += gridDim.x * blockDim.x) {
        float v = s[i];
        __nv_bfloat16 h = __float2bfloat16(v);
        hi[i] = h;
        lo[i] = __float2bfloat16(v - __bfloat162float(h));
    }
}
// fused: scale + split (normal) + transposed split, one pass over w
__global__ void scale_split_trans_kernel(const float* __restrict__ w,
                                         __nv_bfloat16* __restrict__ hi, __nv_bfloat16* __restrict__ lo,
                                         __nv_bfloat16* __restrict__ thi, __nv_bfloat16* __restrict__ tlo) {
    __shared__ float t[32][33];
    const float s = g_scale;
    int x = blockIdx.x * 32 + threadIdx.x;
    int y0 = blockIdx.y * 32;
    for (int j = threadIdx.y; j < 32; j += 8) {
        float v = w[(size_t)(y0 + j) * LD + x] * s;
        t[j][threadIdx.x] = v;
        size_t o = (size_t)(y0 + j) * LD + x;
        __nv_bfloat16 h = __float2bfloat16(v);
        hi[o] = h;
        lo[o] = __float2bfloat16(v - __bfloat162float(h));
    }
    __syncthreads();
    int ox = blockIdx.y * 32 + threadIdx.x;
    for (int j = threadIdx.y; j < 32; j += 8) {
        float v = t[threadIdx.x][j];
        size_t o = (size_t)(blockIdx.x * 32 + j) * LD + ox;
        __nv_bfloat16 h = __float2bfloat16(v);
        thi[o] = h;
        tlo[o] = __float2bfloat16(v - __bfloat162float(h));
    }
}

// ====== TRIANGULAR kernel (modes 0/1): R6 config — 8 warps, 32x64 tiles ======
static constexpr int BM = 128, BN = 128, BKE = 64;
static constexpr int NCH = DIM / BKE;            // 32 chunks
static constexpr int TILE_B = BM * 128;          // 16 KB
static constexpr int STAGE_B = 4 * TILE_B;       // 64 KB
static constexpr int STAGES = 3;
static constexpr int SMEM_TRI = STAGES * STAGE_B;  // 192 KB

template <int MODE>
__global__ __launch_bounds__(256, 1) void mmagemm_tri(
    const __nv_bfloat16* __restrict__ Ahi, const __nv_bfloat16* __restrict__ Alo,
    const __nv_bfloat16* __restrict__ Bhi, const __nv_bfloat16* __restrict__ Blo,
    const __nv_bfloat16* __restrict__ auxhi, const __nv_bfloat16* __restrict__ auxlo,
    __nv_bfloat16* __restrict__ Chi, __nv_bfloat16* __restrict__ Clo) {
    extern __shared__ char sm[];
    const uint32_t smb = smem_u32(sm);
    const int tid = threadIdx.x;
    const int wid = tid >> 5;
    const int lane = tid & 31;

    const int i = blockIdx.x;
    float fq = sqrtf(8.0f * (float)i + 1.0f);
    int tn = (int)((fq - 1.0f) * 0.5f);
    while ((tn + 1) * (tn + 2) / 2 <= i) tn++;
    while (tn * (tn + 1) / 2 > i) tn--;
    int tm = i - tn * (tn + 1) / 2;
    const int bM = tm * BM;
    const int bN = tn * BN;

    const int lr = tid >> 1;
    const int lq0 = (tid & 1) * 4;
    const uint32_t lxor = (uint32_t)(lr & 7);
    auto load_chunk = [&](int c, int s) {
        const uint32_t st = smb + s * STAGE_B;
        const size_t gA = (size_t)(bM + lr) * LD + c * BKE;
        const size_t gB = (size_t)(bN + lr) * LD + c * BKE;
        const uint32_t rowb = st + lr * 128;
#pragma unroll
        for (int q0 = 0; q0 < 4; q0++) {
            const uint32_t q = lq0 + q0;
            const uint32_t so = rowb + ((q ^ lxor) << 4);
            cpa16(so,              Ahi + gA + q * 8);
            cpa16(so + TILE_B,     Alo + gA + q * 8);
            cpa16(so + 2 * TILE_B, Bhi + gB + q * 8);
            cpa16(so + 3 * TILE_B, Blo + gB + q * 8);
        }
    };

    const int wm = wid & 3;
    const int wn = wid >> 2;
    const int arow = wm * 32 + (lane & 15);
    const uint32_t aChunk = (uint32_t)(lane >> 4);
    const uint32_t aXor = (uint32_t)(arow & 7);
    const int brow0 = wn * 64 + (lane & 7) + ((lane >> 4) & 1) * 8;
    const uint32_t bChunk = (uint32_t)((lane >> 3) & 1);
    const uint32_t bXor = (uint32_t)(brow0 & 7);

    float acc[2][8][4];
#pragma unroll
    for (int a = 0; a < 2; a++)
#pragma unroll
        for (int b = 0; b < 8; b++)
#pragma unroll
            for (int q = 0; q < 4; q++) acc[a][b][q] = 0.f;

    load_chunk(0, 0);
    CP_COMMIT();
    load_chunk(1, 1);
    CP_COMMIT();

#pragma unroll 1
    for (int c = 0; c < NCH; c++) {
        CP_WAIT1();
        __syncthreads();
        if (c + 2 < NCH) load_chunk(c + 2, (c + 2) % STAGES);
        CP_COMMIT();

        const uint32_t st = smb + (c % STAGES) * STAGE_B;
#pragma unroll
        for (int kk = 0; kk < 4; kk++) {
            uint32_t ah[2][4], al[2][4];
#pragma unroll
            for (int mt = 0; mt < 2; mt++) {
                const uint32_t addr = st + (uint32_t)(arow + mt * 16) * 128 +
                                      (((kk * 2 + aChunk) ^ aXor) << 4);
                LDMX4(ah[mt], addr);
                LDMX4(al[mt], addr + TILE_B);
            }
            uint32_t bh[4][4], bl[4][4];
#pragma unroll
            for (int nt = 0; nt < 4; nt++) {
                const uint32_t addr = st + 2 * TILE_B +
                                      (uint32_t)(brow0 + nt * 16) * 128 +
                                      (((kk * 2 + bChunk) ^ bXor) << 4);
                LDMX4(bh[nt], addr);
                LDMX4(bl[nt], addr + TILE_B);
            }
#pragma unroll
            for (int mt = 0; mt < 2; mt++)
#pragma unroll
                for (int nt = 0; nt < 4; nt++) {
                    MMA16816(acc[mt][2 * nt],     ah[mt], bh[nt][0], bh[nt][1]);
                    MMA16816(acc[mt][2 * nt],     ah[mt], bl[nt][0], bl[nt][1]);
                    MMA16816(acc[mt][2 * nt],     al[mt], bh[nt][0], bh[nt][1]);
                    MMA16816(acc[mt][2 * nt + 1], ah[mt], bh[nt][2], bh[nt][3]);
                    MMA16816(acc[mt][2 * nt + 1], ah[mt], bl[nt][2], bl[nt][3]);
                    MMA16816(acc[mt][2 * nt + 1], al[mt], bh[nt][2], bh[nt][3]);
                }
        }
    }

    const int qrow = lane >> 2;
    const int qcol = (lane & 3) * 2;
    float* stage = (float*)sm;
    __syncthreads();
#pragma unroll
    for (int mt = 0; mt < 2; mt++) {
#pragma unroll
        for (int h = 0; h < 2; h++) {
            const int rl = wm * 32 + mt * 16 + qrow + h * 8;
#pragma unroll
            for (int n8 = 0; n8 < 8; n8++) {
                const int cl = wn * 64 + n8 * 8 + qcol;
                float v0 = acc[mt][n8][h * 2 + 0];
                float v1 = acc[mt][n8][h * 2 + 1];
                if (MODE == 1) {
                    const size_t ao = (size_t)(bM + rl) * LD + bN + cl;
                    __nv_bfloat162 a2 = *(const __nv_bfloat162*)(auxhi + ao);
                    __nv_bfloat162 l2 = *(const __nv_bfloat162*)(auxlo + ao);
                    v0 = NSC_C * v0 + NSC_B * (__bfloat162float(a2.x) + __bfloat162float(l2.x));
                    v1 = NSC_C * v1 + NSC_B * (__bfloat162float(a2.y) + __bfloat162float(l2.y));
                }
                stage[rl * 128 + (cl ^ (rl & 31))] = v0;
                stage[rl * 128 + ((cl + 1) ^ (rl & 31))] = v1;
            }
        }
    }
    __syncthreads();

    const int c4 = lane * 4;
#pragma unroll 4
    for (int rr = 0; rr < 16; rr++) {
        const int r = wid * 16 + rr;
        const int rx = r & 31;
        float f0 = stage[r * 128 + ((c4 + 0) ^ rx)];
        float f1 = stage[r * 128 + ((c4 + 1) ^ rx)];
        float f2 = stage[r * 128 + ((c4 + 2) ^ rx)];
        float f3 = stage[r * 128 + ((c4 + 3) ^ rx)];
        store_split4(Chi, Clo, (size_t)(bM + r) * LD + bN + c4, f0, f1, f2, f3);
    }
    if (tm != tn) {
#pragma unroll 4
        for (int rr = 0; rr < 16; rr++) {
            const int r = wid * 16 + rr;
            float f0 = stage[(c4 + 0) * 128 + (r ^ ((c4 + 0) & 31))];
            float f1 = stage[(c4 + 1) * 128 + (r ^ ((c4 + 1) & 31))];
            float f2 = stage[(c4 + 2) * 128 + (r ^ ((c4 + 2) & 31))];
            float f3 = stage[(c4 + 3) * 128 + (r ^ ((c4 + 3) & 31))];
            store_split4(Chi, Clo, (size_t)(bN + r) * LD + bM + c4, f0, f1, f2, f3);
        }
    }
}

// ===== BIG kernel (modes 2/3): CTA 128x256, 64x64 warp tile, BK=64 2-stage ===
static constexpr int B2M = 128, B2N = 256, B2K = 64;
static constexpr int NC2 = DIM / B2K;                    // 32 chunks
static constexpr int PITCH = 144;                        // 128B data + 16B pad
static constexpr int A2_B = B2M * PITCH;                 // 18432
static constexpr int B2_B = B2N * PITCH;                 // 36864
static constexpr int STG2 = 2 * A2_B + 2 * B2_B;         // 110592
static constexpr int SMEM_BIG = 2 * STG2;                // 221184

template <int MODE>
__global__ __launch_bounds__(256, 1) void mmagemm_big(
    const __nv_bfloat16* __restrict__ Ahi, const __nv_bfloat16* __restrict__ Alo,
    const __nv_bfloat16* __restrict__ Bhi, const __nv_bfloat16* __restrict__ Blo,
    const __nv_bfloat16* __restrict__ auxhi, const __nv_bfloat16* __restrict__ auxlo,
    const float* __restrict__ bias,
    __nv_bfloat16* __restrict__ Chi, __nv_bfloat16* __restrict__ Clo,
    __nv_bfloat16* __restrict__ Thi, __nv_bfloat16* __restrict__ Tlo,
    float* __restrict__ Cf32) {
    extern __shared__ char sm[];
    const uint32_t smb = smem_u32(sm);
    const int tid = threadIdx.x;
    const int wid = tid >> 5;
    const int lane = tid & 31;
    const int bM = blockIdx.y * B2M;
    const int bN = blockIdx.x * B2N;

    // loader: 384 rows x 8 q of 16B, hi+lo => 12 iterations of (2 cpa16)
    auto load_chunk = [&](int c, int s) {
        const uint32_t st = smb + s * STG2;
#pragma unroll
        for (int it = 0; it < 12; it++) {
            const int i = tid + it * 256;   // 0..3071
            const int row = i >> 3;         // 0..383
            const int q = i & 7;
            if (row < B2M) {
                const size_t g = (size_t)(bM + row) * LD + c * B2K + q * 8;
                const uint32_t so = st + row * PITCH + q * 16;
                cpa16(so, Ahi + g);
                cpa16(so + A2_B, Alo + g);
            } else {
                const int br = row - B2M;
                const size_t g = (size_t)(bN + br) * LD + c * B2K + q * 8;
                const uint32_t so = st + 2 * A2_B + br * PITCH + q * 16;
                cpa16(so, Bhi + g);
                cpa16(so + B2_B, Blo + g);
            }
        }
    };

    const int wm = wid & 1;
    const int wn = wid >> 1;
    const int arowL = wm * 64 + (lane & 15);
    const int aChunk = lane >> 4;
    const int browL = wn * 64 + (lane & 7) + ((lane >> 4) & 1) * 8;
    const int bChunk = (lane >> 3) & 1;

    float acc[4][8][4];
#pragma unroll
    for (int a = 0; a < 4; a++)
#pragma unroll
        for (int b = 0; b < 8; b++)
#pragma unroll
            for (int q = 0; q < 4; q++) acc[a][b][q] = 0.f;

    load_chunk(0, 0);
    CP_COMMIT();

#pragma unroll 1
    for (int c = 0; c < NC2; c++) {
        if (c + 1 < NC2) {
            load_chunk(c + 1, (c + 1) & 1);
            CP_COMMIT();
            CP_WAIT1();
        } else {
            CP_WAIT0();
        }
        __syncthreads();

        const uint32_t st = smb + (c & 1) * STG2;
#pragma unroll
        for (int kk = 0; kk < 4; kk++) {
            uint32_t ah[4][4], al[4][4];
#pragma unroll
            for (int mt = 0; mt < 4; mt++) {
                const uint32_t addr = st + (uint32_t)(arowL + mt * 16) * PITCH +
                                      (uint32_t)(kk * 2 + aChunk) * 16;
                LDMX4(ah[mt], addr);
                LDMX4(al[mt], addr + A2_B);
            }
            uint32_t bh[4][4], bl[4][4];
#pragma unroll
            for (int nt = 0; nt < 4; nt++) {
                const uint32_t addr = st + 2 * A2_B +
                                      (uint32_t)(browL + nt * 16) * PITCH +
                                      (uint32_t)(kk * 2 + bChunk) * 16;
                LDMX4(bh[nt], addr);
                LDMX4(bl[nt], addr + B2_B);
            }
#pragma unroll
            for (int mt = 0; mt < 4; mt++)
#pragma unroll
                for (int nt = 0; nt < 4; nt++) {
                    MMA16816(acc[mt][2 * nt],     ah[mt], bh[nt][0], bh[nt][1]);
                    MMA16816(acc[mt][2 * nt],     ah[mt], bl[nt][0], bl[nt][1]);
                    MMA16816(acc[mt][2 * nt],     al[mt], bh[nt][0], bh[nt][1]);
                    MMA16816(acc[mt][2 * nt + 1], ah[mt], bh[nt][2], bh[nt][3]);
                    MMA16816(acc[mt][2 * nt + 1], ah[mt], bl[nt][2], bl[nt][3]);
                    MMA16816(acc[mt][2 * nt + 1], al[mt], bh[nt][2], bh[nt][3]);
                }
        }
        __syncthreads();
    }

    const int qrow = lane >> 2;
    const int qcol = (lane & 3) * 2;

    if (MODE == 3) {
#pragma unroll
        for (int mt = 0; mt < 4; mt++) {
#pragma unroll
            for (int h = 0; h < 2; h++) {
                const int row = bM + wm * 64 + mt * 16 + qrow + h * 8;
                float* cr = Cf32 + (size_t)row * LD;
#pragma unroll
                for (int n8 = 0; n8 < 8; n8++) {
                    const int col = bN + wn * 64 + n8 * 8 + qcol;
                    float2 b2 = *(const float2*)(bias + col);
                    float2 o;
                    o.x = acc[mt][n8][h * 2 + 0] + b2.x;
                    o.y = acc[mt][n8][h * 2 + 1] + b2.y;
                    *(float2*)(cr + col) = o;
                }
            }
        }
        return;
    }

    // MODE 2: stage 128x256 fp32 (128 KB), swizzle col ^ (row & 31)
    float* stage = (float*)sm;
    __syncthreads();
#pragma unroll
    for (int mt = 0; mt < 4; mt++) {
#pragma unroll
        for (int h = 0; h < 2; h++) {
            const int rl = wm * 64 + mt * 16 + qrow + h * 8;
#pragma unroll
            for (int n8 = 0; n8 < 8; n8++) {
                const int cl = wn * 64 + n8 * 8 + qcol;
                float v0 = acc[mt][n8][h * 2 + 0];
                float v1 = acc[mt][n8][h * 2 + 1];
                const size_t ao = (size_t)(bM + rl) * LD + bN + cl;
                __nv_bfloat162 a2 = *(const __nv_bfloat162*)(auxhi + ao);
                __nv_bfloat162 l2 = *(const __nv_bfloat162*)(auxlo + ao);
                v0 = fmaf(NSC_A, __bfloat162float(a2.x) + __bfloat162float(l2.x), v0);
                v1 = fmaf(NSC_A, __bfloat162float(a2.y) + __bfloat162float(l2.y), v1);
                stage[rl * 256 + (cl ^ (rl & 31))] = v0;
                stage[rl * 256 + ((cl + 1) ^ (rl & 31))] = v1;
            }
        }
    }
    __syncthreads();

    {
        const int cb = lane * 2;
#pragma unroll 2
        for (int rr = 0; rr < 16; rr++) {
            const int r = wid * 16 + rr;
            const int rx = r & 31;
#pragma unroll
            for (int j = 0; j < 4; j++) {
                const int c = cb + 64 * j;
                float f0 = stage[r * 256 + (c ^ rx)];
                float f1 = stage[r * 256 + ((c + 1) ^ rx)];
                store_split2(Chi, Clo, (size_t)(bM + r) * LD + bN + c, f0, f1);
            }
        }
    }
    {
        const int cb = lane * 2;
#pragma unroll 2
        for (int rr = 0; rr < 32; rr++) {
            const int rp = wid * 32 + rr;
#pragma unroll
            for (int j = 0; j < 2; j++) {
                const int cp = cb + 64 * j;
                float f0 = stage[cp * 256 + (rp ^ (cp & 31))];
                float f1 = stage[(cp + 1) * 256 + (rp ^ ((cp + 1) & 31))];
                store_split2(Thi, Tlo, (size_t)(bN + rp) * LD + bM + cp, f0, f1);
            }
        }
    }
}

// ---------------- launch -----------------------------------------------------
extern "C" void kernel_launch(void* const* d_in, const int* in_sizes, int n_in,
                              void* d_out, int out_size) {
    const float* x = nullptr;
    const float* w = nullptr;
    const float* bias = nullptr;
    int x_size = 0;
    for (int i = 0; i < n_in; i++) {
        const int sz = in_sizes[i];
        if (sz == DIM) bias = (const float*)d_in[i];
        else if (sz == DIM * DIM) w = (const float*)d_in[i];
        else { x = (const float*)d_in[i]; x_size = sz; }
    }
    const int B_rows = x_size / DIM;  // 16384
    float* out = (float*)d_out;

    __nv_bfloat16 *pXhi[2], *pXlo[2], *pXThi[2], *pXTlo[2];
    __nv_bfloat16 *pGhi, *pGlo, *pBhi, *pBlo, *pxh, *pxl;
    {
        __nv_bfloat16* base;
        cudaGetSymbolAddress((void**)&base, g_Xhi);
        pXhi[0] = base; pXhi[1] = base + DIM * DIM;
        cudaGetSymbolAddress((void**)&base, g_Xlo);
        pXlo[0] = base; pXlo[1] = base + DIM * DIM;
        cudaGetSymbolAddress((void**)&base, g_XThi);
        pXThi[0] = base; pXThi[1] = base + DIM * DIM;
        cudaGetSymbolAddress((void**)&base, g_XTlo);
        pXTlo[0] = base; pXTlo[1] = base + DIM * DIM;
    }
    cudaGetSymbolAddress((void**)&pGhi, g_Ghi);
    cudaGetSymbolAddress((void**)&pGlo, g_Glo);
    cudaGetSymbolAddress((void**)&pBhi, g_Bhi);
    cudaGetSymbolAddress((void**)&pBlo, g_Blo);
    cudaGetSymbolAddress((void**)&pxh, g_xbig_hi);
    cudaGetSymbolAddress((void**)&pxl, g_xbig_lo);

    cudaFuncSetAttribute(mmagemm_tri<0>, cudaFuncAttributeMaxDynamicSharedMemorySize, SMEM_TRI);
    cudaFuncSetAttribute(mmagemm_tri<1>, cudaFuncAttributeMaxDynamicSharedMemorySize, SMEM_TRI);
    cudaFuncSetAttribute(mmagemm_big<2>, cudaFuncAttributeMaxDynamicSharedMemorySize, SMEM_BIG);
    cudaFuncSetAttribute(mmagemm_big<3>, cudaFuncAttributeMaxDynamicSharedMemorySize, SMEM_BIG);

    const int n = DIM * DIM;
    norm_partial_kernel<<<256, 256>>>(w, n);
    norm_finalize_kernel<<<1, 256>>>();
    scale_split_trans_kernel<<<dim3(64, 64), dim3(32, 8)>>>(
        w, pXhi[0], pXlo[0], pXThi[0], pXTlo[0]);
    split_kernel<<<8192, 256>>>(x, pxh, pxl, B_rows * DIM);

    const int NT = 16;
    dim3 gtri(NT * (NT + 1) / 2, 1);         // 136 CTAs
    dim3 g2(DIM / B2N, DIM / B2M);           // (8, 16) = 128 CTAs
    for (int s = 0; s < 10; s++) {
        const int c0 = s & 1, n1 = c0 ^ 1;
        // G = X @ X^T (symmetric, triangular + mirror)
        mmagemm_tri<0><<<gtri, 256, SMEM_TRI>>>(
            pXhi[c0], pXlo[c0], pXhi[c0], pXlo[c0],
            nullptr, nullptr, pGhi, pGlo);
        // Bm = c*(G@G) + b*G (symmetric, triangular + mirror)
        mmagemm_tri<1><<<gtri, 256, SMEM_TRI>>>(
            pGhi, pGlo, pGhi, pGlo,
            pGhi, pGlo, pBhi, pBlo);
        // X' = Bm@X + a*X ; writes X'[n1] split + X'^T[n1] split
        mmagemm_big<2><<<g2, 256, SMEM_BIG>>>(
            pBhi, pBlo, pXThi[c0], pXTlo[c0],
            pXhi[c0], pXlo[c0], nullptr,
            pXhi[n1], pXlo[n1], pXThi[n1], pXTlo[n1], nullptr);
    }
    // out = x @ Xfinal + bias
    dim3 gout(DIM / B2N, B_rows / B2M);  // (8, 128)
    mmagemm_big<3><<<gout, 256, SMEM_BIG>>>(
        pxh, pxl, pXThi[0], pXTlo[0],
        nullptr, nullptr, bias, nullptr, nullptr, nullptr, nullptr, out);
}

// round 10
// speedup vs baseline: 1.1192x; 1.0393x over previous
#include <cuda_runtime.h>
#include <cuda_bf16.h>
#include <cstdint>
#include <math.h>

static constexpr int DIM = 2048;
static constexpr int LD = 2048;
static constexpr float NSC_A = 3.4445f;
static constexpr float NSC_B = -4.7750f;
static constexpr float NSC_C = 2.0315f;

// ---------------- scratch (allocation-free: __device__ globals) -------------
__device__ __align__(256) __nv_bfloat16 g_Xhi [2][DIM * DIM];
__device__ __align__(256) __nv_bfloat16 g_Xlo [2][DIM * DIM];
__device__ __align__(256) __nv_bfloat16 g_XThi[2][DIM * DIM];
__device__ __align__(256) __nv_bfloat16 g_XTlo[2][DIM * DIM];
__device__ __align__(256) __nv_bfloat16 g_Ghi [DIM * DIM];
__device__ __align__(256) __nv_bfloat16 g_Glo [DIM * DIM];
__device__ __align__(256) __nv_bfloat16 g_Bhi [DIM * DIM];
__device__ __align__(256) __nv_bfloat16 g_Blo [DIM * DIM];
__device__ __align__(256) __nv_bfloat16 g_xbig_hi[16384 * DIM];
__device__ __align__(256) __nv_bfloat16 g_xbig_lo[16384 * DIM];
__device__ float g_partial[256];
__device__ float g_scale;

// ---------------- helpers ----------------------------------------------------
__device__ __forceinline__ uint32_t smem_u32(const void* p) {
    uint32_t a;
    asm("{ .reg .u64 t; cvta.to.shared.u64 t, %1; cvt.u32.u64 %0, t; }" : "=r"(a) : "l"(p));
    return a;
}
__device__ __forceinline__ void cpa16(uint32_t dst, const void* src) {
    asm volatile("cp.async.cg.shared.global [%0], [%1], 16;" :: "r"(dst), "l"(src) : "memory");
}
#define CP_COMMIT() asm volatile("cp.async.commit_group;" ::: "memory")
#define CP_WAIT1()  asm volatile("cp.async.wait_group 1;" ::: "memory")
#define CP_WAIT0()  asm volatile("cp.async.wait_group 0;" ::: "memory")
#define BARG(id)    asm volatile("bar.sync %0, 128;" :: "r"(id) : "memory")

#define LDMX4(r, a)                                                              \
    asm volatile("ldmatrix.sync.aligned.m8n8.x4.shared.b16 {%0,%1,%2,%3}, [%4];" \
        : "=r"((r)[0]), "=r"((r)[1]), "=r"((r)[2]), "=r"((r)[3]) : "r"(a))

#define MMA16816(acc, a, b0, b1)                                                  \
    asm volatile("mma.sync.aligned.m16n8k16.row.col.f32.bf16.bf16.f32 "           \
        "{%0,%1,%2,%3}, {%4,%5,%6,%7}, {%8,%9}, {%0,%1,%2,%3};"                   \
        : "+f"((acc)[0]), "+f"((acc)[1]), "+f"((acc)[2]), "+f"((acc)[3])          \
        : "r"((a)[0]), "r"((a)[1]), "r"((a)[2]), "r"((a)[3]), "r"(b0), "r"(b1))

__device__ __forceinline__ void store_split4(__nv_bfloat16* H, __nv_bfloat16* L, size_t off,
                                             float f0, float f1, float f2, float f3) {
    __nv_bfloat16 h0 = __float2bfloat16(f0), h1 = __float2bfloat16(f1);
    __nv_bfloat16 h2 = __float2bfloat16(f2), h3 = __float2bfloat16(f3);
    __nv_bfloat162 hA, hB, lA, lB;
    hA.x = h0; hA.y = h1; hB.x = h2; hB.y = h3;
    lA.x = __float2bfloat16(f0 - __bfloat162float(h0));
    lA.y = __float2bfloat16(f1 - __bfloat162float(h1));
    lB.x = __float2bfloat16(f2 - __bfloat162float(h2));
    lB.y = __float2bfloat16(f3 - __bfloat162float(h3));
    *(__nv_bfloat162*)(H + off) = hA;
    *(__nv_bfloat162*)(H + off + 2) = hB;
    *(__nv_bfloat162*)(L + off) = lA;
    *(__nv_bfloat162*)(L + off + 2) = lB;
}
__device__ __forceinline__ void store_split2(__nv_bfloat16* H, __nv_bfloat16* L, size_t off,
                                             float f0, float f1) {
    __nv_bfloat16 h0 = __float2bfloat16(f0), h1 = __float2bfloat16(f1);
    __nv_bfloat162 h2, l2;
    h2.x = h0; h2.y = h1;
    l2.x = __float2bfloat16(f0 - __bfloat162float(h0));
    l2.y = __float2bfloat16(f1 - __bfloat162float(h1));
    *(__nv_bfloat162*)(H + off) = h2;
    *(__nv_bfloat162*)(L + off) = l2;
}

// ---------------- small kernels ---------------------------------------------
__global__ void norm_partial_kernel(const float* __restrict__ w, int n) {
    __shared__ float sd[256];
    float s = 0.f;
    for (int i = blockIdx.x * blockDim.x + threadIdx.x; i < n; i += gridDim.x * blockDim.x) {
        float v = w[i];
        s = fmaf(v, v, s);
    }
    sd[threadIdx.x] = s;
    __syncthreads();
    for (int o = 128; o; o >>= 1) {
        if (threadIdx.x < o) sd[threadIdx.x] += sd[threadIdx.x + o];
        __syncthreads();
    }
    if (threadIdx.x == 0) g_partial[blockIdx.x] = sd[0];
}
__global__ void norm_finalize_kernel() {
    __shared__ float sd[256];
    sd[threadIdx.x] = g_partial[threadIdx.x];
    __syncthreads();
    for (int o = 128; o; o >>= 1) {
        if (threadIdx.x < o) sd[threadIdx.x] += sd[threadIdx.x + o];
        __syncthreads();
    }
    if (threadIdx.x == 0) g_scale = 1.0f / (sqrtf(sd[0]) + 1e-7f);
}
// vectorized split: float4 in, 2x bf16x2 out per array
__global__ void split4_kernel(const float4* __restrict__ s,
                              __nv_bfloat162* __restrict__ hi, __nv_bfloat162* __restrict__ lo,
                              int n4) {
    for (int i = blockIdx.x * blockDim.x + threadIdx.x; i < n4; i += gridDim.x * blockDim.x) {
        float4 v = s[i];
        __nv_bfloat16 h0 = __float2bfloat16(v.x), h1 = __float2bfloat16(v.y);
        __nv_bfloat16 h2 = __float2bfloat16(v.z), h3 = __float2bfloat16(v.w);
        __nv_bfloat162 hA, hB, lA, lB;
        hA.x = h0; hA.y = h1; hB.x = h2; hB.y = h3;
        lA.x = __float2bfloat16(v.x - __bfloat162float(h0));
        lA.y = __float2bfloat16(v.y - __bfloat162float(h1));
        lB.x = __float2bfloat16(v.z - __bfloat162float(h2));
        lB.y = __float2bfloat16(v.w - __bfloat162float(h3));
        hi[2 * i] = hA; hi[2 * i + 1] = hB;
        lo[2 * i] = lA; lo[2 * i + 1] = lB;
    }
}
// fused: scale + split (normal) + transposed split, one pass over w
__global__ void scale_split_trans_kernel(const float* __restrict__ w,
                                         __nv_bfloat16* __restrict__ hi, __nv_bfloat16* __restrict__ lo,
                                         __nv_bfloat16* __restrict__ thi, __nv_bfloat16* __restrict__ tlo) {
    __shared__ float t[32][33];
    const float s = g_scale;
    int x = blockIdx.x * 32 + threadIdx.x;
    int y0 = blockIdx.y * 32;
    for (int j = threadIdx.y; j < 32; j += 8) {
        float v = w[(size_t)(y0 + j) * LD + x] * s;
        t[j][threadIdx.x] = v;
        size_t o = (size_t)(y0 + j) * LD + x;
        __nv_bfloat16 h = __float2bfloat16(v);
        hi[o] = h;
        lo[o] = __float2bfloat16(v - __bfloat162float(h));
    }
    __syncthreads();
    int ox = blockIdx.y * 32 + threadIdx.x;
    for (int j = threadIdx.y; j < 32; j += 8) {
        float v = t[threadIdx.x][j];
        size_t o = (size_t)(blockIdx.x * 32 + j) * LD + ox;
        __nv_bfloat16 h = __float2bfloat16(v);
        thi[o] = h;
        tlo[o] = __float2bfloat16(v - __bfloat162float(h));
    }
}

// ====== TRIANGULAR kernel v4 (modes 0/1): two INDEPENDENT split-K groups =====
// Group g (128 threads) owns K range [g*1024, (g+1)*1024), its own smem region,
// its own 2-stage cp.async pipeline and named barrier. 4 warps per group in a
// 2x2 grid of 64x64 warp tiles (ratio-6 MMA:LDSM). No cross-group sync until
// the reduction epilogue.
static constexpr int TK = 32;                  // BK per chunk
static constexpr int NCK = 1024 / TK;          // 32 chunks per group
static constexpr int TPITCH = 80;              // 64B data + 16B pad
static constexpr int TAT = 128 * TPITCH;       // 10240 per tile part
static constexpr int TSTG = 4 * TAT;           // Ahi|Alo|Bhi|Blo = 40960
static constexpr int TGRP = 2 * TSTG;          // 2 stages per group = 81920
static constexpr int SMEM_TRI = 2 * TGRP;      // 163840

template <int MODE>
__global__ __launch_bounds__(256, 1) void mmagemm_tri(
    const __nv_bfloat16* __restrict__ Ahi, const __nv_bfloat16* __restrict__ Alo,
    const __nv_bfloat16* __restrict__ Bhi, const __nv_bfloat16* __restrict__ Blo,
    const __nv_bfloat16* __restrict__ auxhi, const __nv_bfloat16* __restrict__ auxlo,
    __nv_bfloat16* __restrict__ Chi, __nv_bfloat16* __restrict__ Clo) {
    extern __shared__ char sm[];
    const uint32_t smb = smem_u32(sm);
    const int tid = threadIdx.x;
    const int wid = tid >> 5;
    const int lane = tid & 31;
    const int g = tid >> 7;          // group 0/1
    const int tg = tid & 127;        // thread-in-group
    const int wig = (tid >> 5) & 3;  // warp-in-group
    const int barid = 1 + g;

    const int i = blockIdx.x;
    float fq = sqrtf(8.0f * (float)i + 1.0f);
    int tn = (int)((fq - 1.0f) * 0.5f);
    while ((tn + 1) * (tn + 2) / 2 <= i) tn++;
    while (tn * (tn + 1) / 2 > i) tn--;
    int tm = i - tn * (tn + 1) / 2;
    const int bM = tm * 128;
    const int bN = tn * 128;

    const uint32_t gbase = smb + g * TGRP;
    const int kbase = g * 1024;

    // loader: per group per chunk: A/B 128 rows x 4 q(16B) x hi/lo = 2048 cpa16
    // over 128 threads => 16 per thread
    auto load_chunk = [&](int c, int s) {
        const uint32_t st = gbase + s * TSTG;
        const int e0 = kbase + c * TK;
#pragma unroll
        for (int it = 0; it < 8; it++) {
            const int idx = tg + it * 128;      // 0..1023
            const int row = idx >> 3;           // 0..127
            const int q = (idx >> 1) & 3;
            const int ab = idx & 1;             // 0 = A, 1 = B
            const uint32_t so = st + ab * (2 * TAT) + row * TPITCH + q * 16;
            const size_t gg = (size_t)((ab ? bN : bM) + row) * LD + e0 + q * 8;
            cpa16(so, (ab ? Bhi : Ahi) + gg);
            cpa16(so + TAT, (ab ? Blo : Alo) + gg);
        }
    };

    // 2x2 warp grid per group, warp tile 64x64
    const int wm = wig & 1;
    const int wn = wig >> 1;
    const int arowL = wm * 64 + (lane & 15);
    const int aChunk = lane >> 4;
    const int browL = wn * 64 + (lane & 7) + ((lane >> 4) & 1) * 8;
    const int bChunk = (lane >> 3) & 1;

    float acc[4][8][4];
#pragma unroll
    for (int a = 0; a < 4; a++)
#pragma unroll
        for (int b = 0; b < 8; b++)
#pragma unroll
            for (int q = 0; q < 4; q++) acc[a][b][q] = 0.f;

    load_chunk(0, 0);
    CP_COMMIT();

#pragma unroll 1
    for (int c = 0; c < NCK; c++) {
        if (c + 1 < NCK) {
            load_chunk(c + 1, (c + 1) & 1);
            CP_COMMIT();
            CP_WAIT1();
        } else {
            CP_WAIT0();
        }
        BARG(barid);   // chunk c data visible to all group warps

        const uint32_t st = gbase + (c & 1) * TSTG;
#pragma unroll
        for (int kk = 0; kk < 2; kk++) {
            uint32_t ah[4][4], al[4][4];
#pragma unroll
            for (int mt = 0; mt < 4; mt++) {
                const uint32_t addr = st + (uint32_t)(arowL + mt * 16) * TPITCH +
                                      (uint32_t)(kk * 2 + aChunk) * 16;
                LDMX4(ah[mt], addr);
                LDMX4(al[mt], addr + TAT);
            }
            uint32_t bh[4][4], bl[4][4];
#pragma unroll
            for (int nt = 0; nt < 4; nt++) {
                const uint32_t addr = st + 2 * TAT +
                                      (uint32_t)(browL + nt * 16) * TPITCH +
                                      (uint32_t)(kk * 2 + bChunk) * 16;
                LDMX4(bh[nt], addr);
                LDMX4(bl[nt], addr + TAT);
            }
#pragma unroll
            for (int mt = 0; mt < 4; mt++)
#pragma unroll
                for (int nt = 0; nt < 4; nt++) {
                    MMA16816(acc[mt][2 * nt],     ah[mt], bh[nt][0], bh[nt][1]);
                    MMA16816(acc[mt][2 * nt],     ah[mt], bl[nt][0], bl[nt][1]);
                    MMA16816(acc[mt][2 * nt],     al[mt], bh[nt][0], bh[nt][1]);
                    MMA16816(acc[mt][2 * nt + 1], ah[mt], bh[nt][2], bh[nt][3]);
                    MMA16816(acc[mt][2 * nt + 1], ah[mt], bl[nt][2], bl[nt][3]);
                    MMA16816(acc[mt][2 * nt + 1], al[mt], bh[nt][2], bh[nt][3]);
                }
        }
        BARG(barid);   // stage c&1 free for the c+2 load next iteration
    }

    // ---- cross-group reduction through fp32 stage (64 KB) -------------------
    const int qrow = lane >> 2;
    const int qcol = (lane & 3) * 2;
    float* stage = (float*)sm;
    __syncthreads();
    // pass 1: group 0 writes raw partials
    if (g == 0) {
#pragma unroll
        for (int mt = 0; mt < 4; mt++)
#pragma unroll
            for (int h = 0; h < 2; h++) {
                const int rl = wm * 64 + mt * 16 + qrow + h * 8;
#pragma unroll
                for (int n8 = 0; n8 < 8; n8++) {
                    const int cl = wn * 64 + n8 * 8 + qcol;
                    stage[rl * 128 + (cl ^ (rl & 31))] = acc[mt][n8][h * 2 + 0];
                    stage[rl * 128 + ((cl + 1) ^ (rl & 31))] = acc[mt][n8][h * 2 + 1];
                }
            }
    }
    __syncthreads();
    // pass 2: group 1 adds and applies MODE-1 coefficients
    if (g == 1) {
#pragma unroll
        for (int mt = 0; mt < 4; mt++)
#pragma unroll
            for (int h = 0; h < 2; h++) {
                const int rl = wm * 64 + mt * 16 + qrow + h * 8;
#pragma unroll
                for (int n8 = 0; n8 < 8; n8++) {
                    const int cl = wn * 64 + n8 * 8 + qcol;
                    const int s0 = rl * 128 + (cl ^ (rl & 31));
                    const int s1 = rl * 128 + ((cl + 1) ^ (rl & 31));
                    float v0 = stage[s0] + acc[mt][n8][h * 2 + 0];
                    float v1 = stage[s1] + acc[mt][n8][h * 2 + 1];
                    if (MODE == 1) {
                        const size_t ao = (size_t)(bM + rl) * LD + bN + cl;
                        __nv_bfloat162 a2 = *(const __nv_bfloat162*)(auxhi + ao);
                        __nv_bfloat162 l2 = *(const __nv_bfloat162*)(auxlo + ao);
                        v0 = NSC_C * v0 + NSC_B * (__bfloat162float(a2.x) + __bfloat162float(l2.x));
                        v1 = NSC_C * v1 + NSC_B * (__bfloat162float(a2.y) + __bfloat162float(l2.y));
                    }
                    stage[s0] = v0;
                    stage[s1] = v1;
                }
            }
    }
    __syncthreads();

    const int c4 = lane * 4;
#pragma unroll 4
    for (int rr = 0; rr < 16; rr++) {
        const int r = wid * 16 + rr;
        const int rx = r & 31;
        float f0 = stage[r * 128 + ((c4 + 0) ^ rx)];
        float f1 = stage[r * 128 + ((c4 + 1) ^ rx)];
        float f2 = stage[r * 128 + ((c4 + 2) ^ rx)];
        float f3 = stage[r * 128 + ((c4 + 3) ^ rx)];
        store_split4(Chi, Clo, (size_t)(bM + r) * LD + bN + c4, f0, f1, f2, f3);
    }
    if (tm != tn) {
#pragma unroll 4
        for (int rr = 0; rr < 16; rr++) {
            const int r = wid * 16 + rr;
            float f0 = stage[(c4 + 0) * 128 + (r ^ ((c4 + 0) & 31))];
            float f1 = stage[(c4 + 1) * 128 + (r ^ ((c4 + 1) & 31))];
            float f2 = stage[(c4 + 2) * 128 + (r ^ ((c4 + 2) & 31))];
            float f3 = stage[(c4 + 3) * 128 + (r ^ ((c4 + 3) & 31))];
            store_split4(Chi, Clo, (size_t)(bN + r) * LD + bM + c4, f0, f1, f2, f3);
        }
    }
}

// ===== BIG kernel (modes 2/3): CTA 128x256, 64x64 warp tile, BK=64 2-stage ===
static constexpr int B2M = 128, B2N = 256, B2K = 64;
static constexpr int NC2 = DIM / B2K;                    // 32 chunks
static constexpr int PITCH = 144;                        // 128B data + 16B pad
static constexpr int A2_B = B2M * PITCH;                 // 18432
static constexpr int B2_B = B2N * PITCH;                 // 36864
static constexpr int STG2 = 2 * A2_B + 2 * B2_B;         // 110592
static constexpr int SMEM_BIG = 2 * STG2;                // 221184

template <int MODE>
__global__ __launch_bounds__(256, 1) void mmagemm_big(
    const __nv_bfloat16* __restrict__ Ahi, const __nv_bfloat16* __restrict__ Alo,
    const __nv_bfloat16* __restrict__ Bhi, const __nv_bfloat16* __restrict__ Blo,
    const __nv_bfloat16* __restrict__ auxhi, const __nv_bfloat16* __restrict__ auxlo,
    const float* __restrict__ bias,
    __nv_bfloat16* __restrict__ Chi, __nv_bfloat16* __restrict__ Clo,
    __nv_bfloat16* __restrict__ Thi, __nv_bfloat16* __restrict__ Tlo,
    float* __restrict__ Cf32) {
    extern __shared__ char sm[];
    const uint32_t smb = smem_u32(sm);
    const int tid = threadIdx.x;
    const int wid = tid >> 5;
    const int lane = tid & 31;
    const int bM = blockIdx.y * B2M;
    const int bN = blockIdx.x * B2N;

    auto load_chunk = [&](int c, int s) {
        const uint32_t st = smb + s * STG2;
#pragma unroll
        for (int it = 0; it < 12; it++) {
            const int i = tid + it * 256;   // 0..3071
            const int row = i >> 3;         // 0..383
            const int q = i & 7;
            if (row < B2M) {
                const size_t g = (size_t)(bM + row) * LD + c * B2K + q * 8;
                const uint32_t so = st + row * PITCH + q * 16;
                cpa16(so, Ahi + g);
                cpa16(so + A2_B, Alo + g);
            } else {
                const int br = row - B2M;
                const size_t g = (size_t)(bN + br) * LD + c * B2K + q * 8;
                const uint32_t so = st + 2 * A2_B + br * PITCH + q * 16;
                cpa16(so, Bhi + g);
                cpa16(so + B2_B, Blo + g);
            }
        }
    };

    const int wm = wid & 1;
    const int wn = wid >> 1;
    const int arowL = wm * 64 + (lane & 15);
    const int aChunk = lane >> 4;
    const int browL = wn * 64 + (lane & 7) + ((lane >> 4) & 1) * 8;
    const int bChunk = (lane >> 3) & 1;

    float acc[4][8][4];
#pragma unroll
    for (int a = 0; a < 4; a++)
#pragma unroll
        for (int b = 0; b < 8; b++)
#pragma unroll
            for (int q = 0; q < 4; q++) acc[a][b][q] = 0.f;

    load_chunk(0, 0);
    CP_COMMIT();

#pragma unroll 1
    for (int c = 0; c < NC2; c++) {
        if (c + 1 < NC2) {
            load_chunk(c + 1, (c + 1) & 1);
            CP_COMMIT();
            CP_WAIT1();
        } else {
            CP_WAIT0();
        }
        __syncthreads();

        const uint32_t st = smb + (c & 1) * STG2;
#pragma unroll
        for (int kk = 0; kk < 4; kk++) {
            uint32_t ah[4][4], al[4][4];
#pragma unroll
            for (int mt = 0; mt < 4; mt++) {
                const uint32_t addr = st + (uint32_t)(arowL + mt * 16) * PITCH +
                                      (uint32_t)(kk * 2 + aChunk) * 16;
                LDMX4(ah[mt], addr);
                LDMX4(al[mt], addr + A2_B);
            }
            uint32_t bh[4][4], bl[4][4];
#pragma unroll
            for (int nt = 0; nt < 4; nt++) {
                const uint32_t addr = st + 2 * A2_B +
                                      (uint32_t)(browL + nt * 16) * PITCH +
                                      (uint32_t)(kk * 2 + bChunk) * 16;
                LDMX4(bh[nt], addr);
                LDMX4(bl[nt], addr + B2_B);
            }
#pragma unroll
            for (int mt = 0; mt < 4; mt++)
#pragma unroll
                for (int nt = 0; nt < 4; nt++) {
                    MMA16816(acc[mt][2 * nt],     ah[mt], bh[nt][0], bh[nt][1]);
                    MMA16816(acc[mt][2 * nt],     ah[mt], bl[nt][0], bl[nt][1]);
                    MMA16816(acc[mt][2 * nt],     al[mt], bh[nt][0], bh[nt][1]);
                    MMA16816(acc[mt][2 * nt + 1], ah[mt], bh[nt][2], bh[nt][3]);
                    MMA16816(acc[mt][2 * nt + 1], ah[mt], bl[nt][2], bl[nt][3]);
                    MMA16816(acc[mt][2 * nt + 1], al[mt], bh[nt][2], bh[nt][3]);
                }
        }
        __syncthreads();
    }

    const int qrow = lane >> 2;
    const int qcol = (lane & 3) * 2;

    if (MODE == 3) {
#pragma unroll
        for (int mt = 0; mt < 4; mt++) {
#pragma unroll
            for (int h = 0; h < 2; h++) {
                const int row = bM + wm * 64 + mt * 16 + qrow + h * 8;
                float* cr = Cf32 + (size_t)row * LD;
#pragma unroll
                for (int n8 = 0; n8 < 8; n8++) {
                    const int col = bN + wn * 64 + n8 * 8 + qcol;
                    float2 b2 = *(const float2*)(bias + col);
                    float2 o;
                    o.x = acc[mt][n8][h * 2 + 0] + b2.x;
                    o.y = acc[mt][n8][h * 2 + 1] + b2.y;
                    *(float2*)(cr + col) = o;
                }
            }
        }
        return;
    }

    // MODE 2: stage 128x256 fp32 (128 KB), swizzle col ^ (row & 31)
    float* stage = (float*)sm;
    __syncthreads();
#pragma unroll
    for (int mt = 0; mt < 4; mt++) {
#pragma unroll
        for (int h = 0; h < 2; h++) {
            const int rl = wm * 64 + mt * 16 + qrow + h * 8;
#pragma unroll
            for (int n8 = 0; n8 < 8; n8++) {
                const int cl = wn * 64 + n8 * 8 + qcol;
                float v0 = acc[mt][n8][h * 2 + 0];
                float v1 = acc[mt][n8][h * 2 + 1];
                const size_t ao = (size_t)(bM + rl) * LD + bN + cl;
                __nv_bfloat162 a2 = *(const __nv_bfloat162*)(auxhi + ao);
                __nv_bfloat162 l2 = *(const __nv_bfloat162*)(auxlo + ao);
                v0 = fmaf(NSC_A, __bfloat162float(a2.x) + __bfloat162float(l2.x), v0);
                v1 = fmaf(NSC_A, __bfloat162float(a2.y) + __bfloat162float(l2.y), v1);
                stage[rl * 256 + (cl ^ (rl & 31))] = v0;
                stage[rl * 256 + ((cl + 1) ^ (rl & 31))] = v1;
            }
        }
    }
    __syncthreads();

    {
        const int cb = lane * 2;
#pragma unroll 2
        for (int rr = 0; rr < 16; rr++) {
            const int r = wid * 16 + rr;
            const int rx = r & 31;
#pragma unroll
            for (int j = 0; j < 4; j++) {
                const int c = cb + 64 * j;
                float f0 = stage[r * 256 + (c ^ rx)];
                float f1 = stage[r * 256 + ((c + 1) ^ rx)];
                store_split2(Chi, Clo, (size_t)(bM + r) * LD + bN + c, f0, f1);
            }
        }
    }
    {
        const int cb = lane * 2;
#pragma unroll 2
        for (int rr = 0; rr < 32; rr++) {
            const int rp = wid * 32 + rr;
#pragma unroll
            for (int j = 0; j < 2; j++) {
                const int cp = cb + 64 * j;
                float f0 = stage[cp * 256 + (rp ^ (cp & 31))];
                float f1 = stage[(cp + 1) * 256 + (rp ^ ((cp + 1) & 31))];
                store_split2(Thi, Tlo, (size_t)(bN + rp) * LD + bM + cp, f0, f1);
            }
        }
    }
}

// ---------------- launch -----------------------------------------------------
extern "C" void kernel_launch(void* const* d_in, const int* in_sizes, int n_in,
                              void* d_out, int out_size) {
    const float* x = nullptr;
    const float* w = nullptr;
    const float* bias = nullptr;
    int x_size = 0;
    for (int i = 0; i < n_in; i++) {
        const int sz = in_sizes[i];
        if (sz == DIM) bias = (const float*)d_in[i];
        else if (sz == DIM * DIM) w = (const float*)d_in[i];
        else { x = (const float*)d_in[i]; x_size = sz; }
    }
    const int B_rows = x_size / DIM;  // 16384
    float* out = (float*)d_out;

    __nv_bfloat16 *pXhi[2], *pXlo[2], *pXThi[2], *pXTlo[2];
    __nv_bfloat16 *pGhi, *pGlo, *pBhi, *pBlo, *pxh, *pxl;
    {
        __nv_bfloat16* base;
        cudaGetSymbolAddress((void**)&base, g_Xhi);
        pXhi[0] = base; pXhi[1] = base + DIM * DIM;
        cudaGetSymbolAddress((void**)&base, g_Xlo);
        pXlo[0] = base; pXlo[1] = base + DIM * DIM;
        cudaGetSymbolAddress((void**)&base, g_XThi);
        pXThi[0] = base; pXThi[1] = base + DIM * DIM;
        cudaGetSymbolAddress((void**)&base, g_XTlo);
        pXTlo[0] = base; pXTlo[1] = base + DIM * DIM;
    }
    cudaGetSymbolAddress((void**)&pGhi, g_Ghi);
    cudaGetSymbolAddress((void**)&pGlo, g_Glo);
    cudaGetSymbolAddress((void**)&pBhi, g_Bhi);
    cudaGetSymbolAddress((void**)&pBlo, g_Blo);
    cudaGetSymbolAddress((void**)&pxh, g_xbig_hi);
    cudaGetSymbolAddress((void**)&pxl, g_xbig_lo);

    cudaFuncSetAttribute(mmagemm_tri<0>, cudaFuncAttributeMaxDynamicSharedMemorySize, SMEM_TRI);
    cudaFuncSetAttribute(mmagemm_tri<1>, cudaFuncAttributeMaxDynamicSharedMemorySize, SMEM_TRI);
    cudaFuncSetAttribute(mmagemm_big<2>, cudaFuncAttributeMaxDynamicSharedMemorySize, SMEM_BIG);
    cudaFuncSetAttribute(mmagemm_big<3>, cudaFuncAttributeMaxDynamicSharedMemorySize, SMEM_BIG);

    const int n = DIM * DIM;
    norm_partial_kernel<<<256, 256>>>(w, n);
    norm_finalize_kernel<<<1, 256>>>();
    scale_split_trans_kernel<<<dim3(64, 64), dim3(32, 8)>>>(
        w, pXhi[0], pXlo[0], pXThi[0], pXTlo[0]);
    split4_kernel<<<4096, 256>>>((const float4*)x, (__nv_bfloat162*)pxh,
                                 (__nv_bfloat162*)pxl, B_rows * DIM / 4);

    const int NT = 16;
    dim3 gtri(NT * (NT + 1) / 2, 1);         // 136 CTAs
    dim3 g2(DIM / B2N, DIM / B2M);           // (8, 16) = 128 CTAs
    for (int s = 0; s < 10; s++) {
        const int c0 = s & 1, n1 = c0 ^ 1;
        // G = X @ X^T (symmetric, triangular + mirror)
        mmagemm_tri<0><<<gtri, 256, SMEM_TRI>>>(
            pXhi[c0], pXlo[c0], pXhi[c0], pXlo[c0],
            nullptr, nullptr, pGhi, pGlo);
        // Bm = c*(G@G) + b*G (symmetric, triangular + mirror)
        mmagemm_tri<1><<<gtri, 256, SMEM_TRI>>>(
            pGhi, pGlo, pGhi, pGlo,
            pGhi, pGlo, pBhi, pBlo);
        // X' = Bm@X + a*X ; writes X'[n1] split + X'^T[n1] split
        mmagemm_big<2><<<g2, 256, SMEM_BIG>>>(
            pBhi, pBlo, pXThi[c0], pXTlo[c0],
            pXhi[c0], pXlo[c0], nullptr,
            pXhi[n1], pXlo[n1], pXThi[n1], pXTlo[n1], nullptr);
    }
    // out = x @ Xfinal + bias
    dim3 gout(DIM / B2N, B_rows / B2M);  // (8, 128)
    mmagemm_big<3><<<gout, 256, SMEM_BIG>>>(
        pxh, pxl, pXThi[0], pXTlo[0],
        nullptr, nullptr, bias, nullptr, nullptr, nullptr, nullptr, out);
}

// round 11
// speedup vs baseline: 1.2002x; 1.0724x over previous
#include <cuda_runtime.h>
#include <cuda_bf16.h>
#include <cuda_fp16.h>
#include <cstdint>
#include <math.h>

static constexpr int DIM = 2048;
static constexpr int LD = 2048;
static constexpr float NSC_A = 3.4445f;
static constexpr float NSC_B = -4.7750f;
static constexpr float NSC_C = 2.0315f;

// ---------------- scratch (allocation-free: __device__ globals) -------------
__device__ __align__(256) __nv_bfloat16 g_Xhi [2][DIM * DIM];
__device__ __align__(256) __nv_bfloat16 g_Xlo [2][DIM * DIM];
__device__ __align__(256) __nv_bfloat16 g_XThi[2][DIM * DIM];
__device__ __align__(256) __nv_bfloat16 g_XTlo[2][DIM * DIM];
__device__ __align__(256) __nv_bfloat16 g_Ghi [DIM * DIM];
__device__ __align__(256) __nv_bfloat16 g_Glo [DIM * DIM];
__device__ __align__(256) __nv_bfloat16 g_Bhi [DIM * DIM];
__device__ __align__(256) __nv_bfloat16 g_Blo [DIM * DIM];
__device__ __align__(256) __half g_x16[16384 * DIM];
__device__ __align__(256) __half g_WTh16[DIM * DIM];
__device__ __align__(256) __half g_WTl16[DIM * DIM];
__device__ float g_partial[256];
__device__ float g_scale;

// ---------------- helpers ----------------------------------------------------
__device__ __forceinline__ uint32_t smem_u32(const void* p) {
    uint32_t a;
    asm("{ .reg .u64 t; cvta.to.shared.u64 t, %1; cvt.u32.u64 %0, t; }" : "=r"(a) : "l"(p));
    return a;
}
__device__ __forceinline__ void cpa16(uint32_t dst, const void* src) {
    asm volatile("cp.async.cg.shared.global [%0], [%1], 16;" :: "r"(dst), "l"(src) : "memory");
}
#define CP_COMMIT() asm volatile("cp.async.commit_group;" ::: "memory")
#define CP_WAIT1()  asm volatile("cp.async.wait_group 1;" ::: "memory")
#define CP_WAIT0()  asm volatile("cp.async.wait_group 0;" ::: "memory")
#define BARG(id)    asm volatile("bar.sync %0, 128;" :: "r"(id) : "memory")

#define LDMX4(r, a)                                                              \
    asm volatile("ldmatrix.sync.aligned.m8n8.x4.shared.b16 {%0,%1,%2,%3}, [%4];" \
        : "=r"((r)[0]), "=r"((r)[1]), "=r"((r)[2]), "=r"((r)[3]) : "r"(a))

#define MMA16816(acc, a, b0, b1)                                                  \
    asm volatile("mma.sync.aligned.m16n8k16.row.col.f32.bf16.bf16.f32 "           \
        "{%0,%1,%2,%3}, {%4,%5,%6,%7}, {%8,%9}, {%0,%1,%2,%3};"                   \
        : "+f"((acc)[0]), "+f"((acc)[1]), "+f"((acc)[2]), "+f"((acc)[3])          \
        : "r"((a)[0]), "r"((a)[1]), "r"((a)[2]), "r"((a)[3]), "r"(b0), "r"(b1))

#define MMAH16816(acc, a, b0, b1)                                                 \
    asm volatile("mma.sync.aligned.m16n8k16.row.col.f32.f16.f16.f32 "             \
        "{%0,%1,%2,%3}, {%4,%5,%6,%7}, {%8,%9}, {%0,%1,%2,%3};"                   \
        : "+f"((acc)[0]), "+f"((acc)[1]), "+f"((acc)[2]), "+f"((acc)[3])          \
        : "r"((a)[0]), "r"((a)[1]), "r"((a)[2]), "r"((a)[3]), "r"(b0), "r"(b1))

__device__ __forceinline__ void store_split4(__nv_bfloat16* H, __nv_bfloat16* L, size_t off,
                                             float f0, float f1, float f2, float f3) {
    __nv_bfloat16 h0 = __float2bfloat16(f0), h1 = __float2bfloat16(f1);
    __nv_bfloat16 h2 = __float2bfloat16(f2), h3 = __float2bfloat16(f3);
    __nv_bfloat162 hA, hB, lA, lB;
    hA.x = h0; hA.y = h1; hB.x = h2; hB.y = h3;
    lA.x = __float2bfloat16(f0 - __bfloat162float(h0));
    lA.y = __float2bfloat16(f1 - __bfloat162float(h1));
    lB.x = __float2bfloat16(f2 - __bfloat162float(h2));
    lB.y = __float2bfloat16(f3 - __bfloat162float(h3));
    *(__nv_bfloat162*)(H + off) = hA;
    *(__nv_bfloat162*)(H + off + 2) = hB;
    *(__nv_bfloat162*)(L + off) = lA;
    *(__nv_bfloat162*)(L + off + 2) = lB;
}
__device__ __forceinline__ void store_split2(__nv_bfloat16* H, __nv_bfloat16* L, size_t off,
                                             float f0, float f1) {
    __nv_bfloat16 h0 = __float2bfloat16(f0), h1 = __float2bfloat16(f1);
    __nv_bfloat162 h2, l2;
    h2.x = h0; h2.y = h1;
    l2.x = __float2bfloat16(f0 - __bfloat162float(h0));
    l2.y = __float2bfloat16(f1 - __bfloat162float(h1));
    *(__nv_bfloat162*)(H + off) = h2;
    *(__nv_bfloat162*)(L + off) = l2;
}
__device__ __forceinline__ void store_split2h(__half* H, __half* L, size_t off,
                                              float f0, float f1) {
    __half h0 = __float2half_rn(f0), h1 = __float2half_rn(f1);
    __half2 h2, l2;
    h2.x = h0; h2.y = h1;
    l2.x = __float2half_rn(f0 - __half2float(h0));
    l2.y = __float2half_rn(f1 - __half2float(h1));
    *(__half2*)(H + off) = h2;
    *(__half2*)(L + off) = l2;
}

// ---------------- small kernels ---------------------------------------------
__global__ void norm_partial_kernel(const float* __restrict__ w, int n) {
    __shared__ float sd[256];
    float s = 0.f;
    for (int i = blockIdx.x * blockDim.x + threadIdx.x; i < n; i += gridDim.x * blockDim.x) {
        float v = w[i];
        s = fmaf(v, v, s);
    }
    sd[threadIdx.x] = s;
    __syncthreads();
    for (int o = 128; o; o >>= 1) {
        if (threadIdx.x < o) sd[threadIdx.x] += sd[threadIdx.x + o];
        __syncthreads();
    }
    if (threadIdx.x == 0) g_partial[blockIdx.x] = sd[0];
}
__global__ void norm_finalize_kernel() {
    __shared__ float sd[256];
    sd[threadIdx.x] = g_partial[threadIdx.x];
    __syncthreads();
    for (int o = 128; o; o >>= 1) {
        if (threadIdx.x < o) sd[threadIdx.x] += sd[threadIdx.x + o];
        __syncthreads();
    }
    if (threadIdx.x == 0) g_scale = 1.0f / (sqrtf(sd[0]) + 1e-7f);
}
// fp32 -> single fp16 convert, float4 vectorized
__global__ void cvt16_kernel(const float4* __restrict__ s, __half2* __restrict__ o, int n4) {
    for (int i = blockIdx.x * blockDim.x + threadIdx.x; i < n4; i += gridDim.x * blockDim.x) {
        float4 v = s[i];
        __half2 a, b;
        a.x = __float2half_rn(v.x); a.y = __float2half_rn(v.y);
        b.x = __float2half_rn(v.z); b.y = __float2half_rn(v.w);
        o[2 * i] = a;
        o[2 * i + 1] = b;
    }
}
// fused: scale + split (normal) + transposed split, one pass over w
__global__ void scale_split_trans_kernel(const float* __restrict__ w,
                                         __nv_bfloat16* __restrict__ hi, __nv_bfloat16* __restrict__ lo,
                                         __nv_bfloat16* __restrict__ thi, __nv_bfloat16* __restrict__ tlo) {
    __shared__ float t[32][33];
    const float s = g_scale;
    int x = blockIdx.x * 32 + threadIdx.x;
    int y0 = blockIdx.y * 32;
    for (int j = threadIdx.y; j < 32; j += 8) {
        float v = w[(size_t)(y0 + j) * LD + x] * s;
        t[j][threadIdx.x] = v;
        size_t o = (size_t)(y0 + j) * LD + x;
        __nv_bfloat16 h = __float2bfloat16(v);
        hi[o] = h;
        lo[o] = __float2bfloat16(v - __bfloat162float(h));
    }
    __syncthreads();
    int ox = blockIdx.y * 32 + threadIdx.x;
    for (int j = threadIdx.y; j < 32; j += 8) {
        float v = t[threadIdx.x][j];
        size_t o = (size_t)(blockIdx.x * 32 + j) * LD + ox;
        __nv_bfloat16 h = __float2bfloat16(v);
        thi[o] = h;
        tlo[o] = __float2bfloat16(v - __bfloat162float(h));
    }
}

// ====== TRIANGULAR kernel (modes 0/1): two INDEPENDENT split-K groups ========
static constexpr int TK = 32;
static constexpr int NCK = 1024 / TK;          // 32 chunks per group
static constexpr int TPITCH = 80;
static constexpr int TAT = 128 * TPITCH;       // 10240
static constexpr int TSTG = 4 * TAT;           // 40960
static constexpr int TGRP = 2 * TSTG;          // 81920
static constexpr int SMEM_TRI = 2 * TGRP;      // 163840

template <int MODE>
__global__ __launch_bounds__(256, 1) void mmagemm_tri(
    const __nv_bfloat16* __restrict__ Ahi, const __nv_bfloat16* __restrict__ Alo,
    const __nv_bfloat16* __restrict__ Bhi, const __nv_bfloat16* __restrict__ Blo,
    const __nv_bfloat16* __restrict__ auxhi, const __nv_bfloat16* __restrict__ auxlo,
    __nv_bfloat16* __restrict__ Chi, __nv_bfloat16* __restrict__ Clo) {
    extern __shared__ char sm[];
    const uint32_t smb = smem_u32(sm);
    const int tid = threadIdx.x;
    const int wid = tid >> 5;
    const int lane = tid & 31;
    const int g = tid >> 7;
    const int tg = tid & 127;
    const int wig = (tid >> 5) & 3;
    const int barid = 1 + g;

    const int i = blockIdx.x;
    float fq = sqrtf(8.0f * (float)i + 1.0f);
    int tn = (int)((fq - 1.0f) * 0.5f);
    while ((tn + 1) * (tn + 2) / 2 <= i) tn++;
    while (tn * (tn + 1) / 2 > i) tn--;
    int tm = i - tn * (tn + 1) / 2;
    const int bM = tm * 128;
    const int bN = tn * 128;

    const uint32_t gbase = smb + g * TGRP;
    const int kbase = g * 1024;

    auto load_chunk = [&](int c, int s) {
        const uint32_t st = gbase + s * TSTG;
        const int e0 = kbase + c * TK;
#pragma unroll
        for (int it = 0; it < 8; it++) {
            const int idx = tg + it * 128;
            const int row = idx >> 3;
            const int q = (idx >> 1) & 3;
            const int ab = idx & 1;
            const uint32_t so = st + ab * (2 * TAT) + row * TPITCH + q * 16;
            const size_t gg = (size_t)((ab ? bN : bM) + row) * LD + e0 + q * 8;
            cpa16(so, (ab ? Bhi : Ahi) + gg);
            cpa16(so + TAT, (ab ? Blo : Alo) + gg);
        }
    };

    const int wm = wig & 1;
    const int wn = wig >> 1;
    const int arowL = wm * 64 + (lane & 15);
    const int aChunk = lane >> 4;
    const int browL = wn * 64 + (lane & 7) + ((lane >> 4) & 1) * 8;
    const int bChunk = (lane >> 3) & 1;

    float acc[4][8][4];
#pragma unroll
    for (int a = 0; a < 4; a++)
#pragma unroll
        for (int b = 0; b < 8; b++)
#pragma unroll
            for (int q = 0; q < 4; q++) acc[a][b][q] = 0.f;

    load_chunk(0, 0);
    CP_COMMIT();

#pragma unroll 1
    for (int c = 0; c < NCK; c++) {
        if (c + 1 < NCK) {
            load_chunk(c + 1, (c + 1) & 1);
            CP_COMMIT();
            CP_WAIT1();
        } else {
            CP_WAIT0();
        }
        BARG(barid);

        const uint32_t st = gbase + (c & 1) * TSTG;
#pragma unroll
        for (int kk = 0; kk < 2; kk++) {
            uint32_t ah[4][4], al[4][4];
#pragma unroll
            for (int mt = 0; mt < 4; mt++) {
                const uint32_t addr = st + (uint32_t)(arowL + mt * 16) * TPITCH +
                                      (uint32_t)(kk * 2 + aChunk) * 16;
                LDMX4(ah[mt], addr);
                LDMX4(al[mt], addr + TAT);
            }
            uint32_t bh[4][4], bl[4][4];
#pragma unroll
            for (int nt = 0; nt < 4; nt++) {
                const uint32_t addr = st + 2 * TAT +
                                      (uint32_t)(browL + nt * 16) * TPITCH +
                                      (uint32_t)(kk * 2 + bChunk) * 16;
                LDMX4(bh[nt], addr);
                LDMX4(bl[nt], addr + TAT);
            }
#pragma unroll
            for (int mt = 0; mt < 4; mt++)
#pragma unroll
                for (int nt = 0; nt < 4; nt++) {
                    MMA16816(acc[mt][2 * nt],     ah[mt], bh[nt][0], bh[nt][1]);
                    MMA16816(acc[mt][2 * nt],     ah[mt], bl[nt][0], bl[nt][1]);
                    MMA16816(acc[mt][2 * nt],     al[mt], bh[nt][0], bh[nt][1]);
                    MMA16816(acc[mt][2 * nt + 1], ah[mt], bh[nt][2], bh[nt][3]);
                    MMA16816(acc[mt][2 * nt + 1], ah[mt], bl[nt][2], bl[nt][3]);
                    MMA16816(acc[mt][2 * nt + 1], al[mt], bh[nt][2], bh[nt][3]);
                }
        }
        BARG(barid);
    }

    // ---- cross-group reduction through fp32 stage ---------------------------
    const int qrow = lane >> 2;
    const int qcol = (lane & 3) * 2;
    float* stage = (float*)sm;
    __syncthreads();
    if (g == 0) {
#pragma unroll
        for (int mt = 0; mt < 4; mt++)
#pragma unroll
            for (int h = 0; h < 2; h++) {
                const int rl = wm * 64 + mt * 16 + qrow + h * 8;
#pragma unroll
                for (int n8 = 0; n8 < 8; n8++) {
                    const int cl = wn * 64 + n8 * 8 + qcol;
                    stage[rl * 128 + (cl ^ (rl & 31))] = acc[mt][n8][h * 2 + 0];
                    stage[rl * 128 + ((cl + 1) ^ (rl & 31))] = acc[mt][n8][h * 2 + 1];
                }
            }
    }
    __syncthreads();
    if (g == 1) {
#pragma unroll
        for (int mt = 0; mt < 4; mt++)
#pragma unroll
            for (int h = 0; h < 2; h++) {
                const int rl = wm * 64 + mt * 16 + qrow + h * 8;
#pragma unroll
                for (int n8 = 0; n8 < 8; n8++) {
                    const int cl = wn * 64 + n8 * 8 + qcol;
                    const int s0 = rl * 128 + (cl ^ (rl & 31));
                    const int s1 = rl * 128 + ((cl + 1) ^ (rl & 31));
                    float v0 = stage[s0] + acc[mt][n8][h * 2 + 0];
                    float v1 = stage[s1] + acc[mt][n8][h * 2 + 1];
                    if (MODE == 1) {
                        const size_t ao = (size_t)(bM + rl) * LD + bN + cl;
                        __nv_bfloat162 a2 = *(const __nv_bfloat162*)(auxhi + ao);
                        __nv_bfloat162 l2 = *(const __nv_bfloat162*)(auxlo + ao);
                        v0 = NSC_C * v0 + NSC_B * (__bfloat162float(a2.x) + __bfloat162float(l2.x));
                        v1 = NSC_C * v1 + NSC_B * (__bfloat162float(a2.y) + __bfloat162float(l2.y));
                    }
                    stage[s0] = v0;
                    stage[s1] = v1;
                }
            }
    }
    __syncthreads();

    const int c4 = lane * 4;
#pragma unroll 4
    for (int rr = 0; rr < 16; rr++) {
        const int r = wid * 16 + rr;
        const int rx = r & 31;
        float f0 = stage[r * 128 + ((c4 + 0) ^ rx)];
        float f1 = stage[r * 128 + ((c4 + 1) ^ rx)];
        float f2 = stage[r * 128 + ((c4 + 2) ^ rx)];
        float f3 = stage[r * 128 + ((c4 + 3) ^ rx)];
        store_split4(Chi, Clo, (size_t)(bM + r) * LD + bN + c4, f0, f1, f2, f3);
    }
    if (tm != tn) {
#pragma unroll 4
        for (int rr = 0; rr < 16; rr++) {
            const int r = wid * 16 + rr;
            float f0 = stage[(c4 + 0) * 128 + (r ^ ((c4 + 0) & 31))];
            float f1 = stage[(c4 + 1) * 128 + (r ^ ((c4 + 1) & 31))];
            float f2 = stage[(c4 + 2) * 128 + (r ^ ((c4 + 2) & 31))];
            float f3 = stage[(c4 + 3) * 128 + (r ^ ((c4 + 3) & 31))];
            store_split4(Chi, Clo, (size_t)(bN + r) * LD + bM + c4, f0, f1, f2, f3);
        }
    }
}

// ===== BIG kernel (mode 2): CTA 128x256, 64x64 warp tile, BK=64 2-stage ======
// LASTF16=0: writes split bf16 C + transposed split bf16 T (NS loop)
// LASTF16=1: skips C; writes transposed split FP16 T (feeds final fp16 GEMM)
static constexpr int B2M = 128, B2N = 256, B2K = 64;
static constexpr int NC2 = DIM / B2K;                    // 32 chunks
static constexpr int PITCH = 144;
static constexpr int A2_B = B2M * PITCH;                 // 18432
static constexpr int B2_B = B2N * PITCH;                 // 36864
static constexpr int STG2 = 2 * A2_B + 2 * B2_B;         // 110592
static constexpr int SMEM_BIG = 2 * STG2;                // 221184

template <int LASTF16>
__global__ __launch_bounds__(256, 1) void mmagemm_big(
    const __nv_bfloat16* __restrict__ Ahi, const __nv_bfloat16* __restrict__ Alo,
    const __nv_bfloat16* __restrict__ Bhi, const __nv_bfloat16* __restrict__ Blo,
    const __nv_bfloat16* __restrict__ auxhi, const __nv_bfloat16* __restrict__ auxlo,
    __nv_bfloat16* __restrict__ Chi, __nv_bfloat16* __restrict__ Clo,
    void* __restrict__ Tp_hi, void* __restrict__ Tp_lo) {
    extern __shared__ char sm[];
    const uint32_t smb = smem_u32(sm);
    const int tid = threadIdx.x;
    const int wid = tid >> 5;
    const int lane = tid & 31;
    const int bM = blockIdx.y * B2M;
    const int bN = blockIdx.x * B2N;

    auto load_chunk = [&](int c, int s) {
        const uint32_t st = smb + s * STG2;
#pragma unroll
        for (int it = 0; it < 12; it++) {
            const int i = tid + it * 256;
            const int row = i >> 3;
            const int q = i & 7;
            if (row < B2M) {
                const size_t g = (size_t)(bM + row) * LD + c * B2K + q * 8;
                const uint32_t so = st + row * PITCH + q * 16;
                cpa16(so, Ahi + g);
                cpa16(so + A2_B, Alo + g);
            } else {
                const int br = row - B2M;
                const size_t g = (size_t)(bN + br) * LD + c * B2K + q * 8;
                const uint32_t so = st + 2 * A2_B + br * PITCH + q * 16;
                cpa16(so, Bhi + g);
                cpa16(so + B2_B, Blo + g);
            }
        }
    };

    const int wm = wid & 1;
    const int wn = wid >> 1;
    const int arowL = wm * 64 + (lane & 15);
    const int aChunk = lane >> 4;
    const int browL = wn * 64 + (lane & 7) + ((lane >> 4) & 1) * 8;
    const int bChunk = (lane >> 3) & 1;

    float acc[4][8][4];
#pragma unroll
    for (int a = 0; a < 4; a++)
#pragma unroll
        for (int b = 0; b < 8; b++)
#pragma unroll
            for (int q = 0; q < 4; q++) acc[a][b][q] = 0.f;

    load_chunk(0, 0);
    CP_COMMIT();

#pragma unroll 1
    for (int c = 0; c < NC2; c++) {
        if (c + 1 < NC2) {
            load_chunk(c + 1, (c + 1) & 1);
            CP_COMMIT();
            CP_WAIT1();
        } else {
            CP_WAIT0();
        }
        __syncthreads();

        const uint32_t st = smb + (c & 1) * STG2;
#pragma unroll
        for (int kk = 0; kk < 4; kk++) {
            uint32_t ah[4][4], al[4][4];
#pragma unroll
            for (int mt = 0; mt < 4; mt++) {
                const uint32_t addr = st + (uint32_t)(arowL + mt * 16) * PITCH +
                                      (uint32_t)(kk * 2 + aChunk) * 16;
                LDMX4(ah[mt], addr);
                LDMX4(al[mt], addr + A2_B);
            }
            uint32_t bh[4][4], bl[4][4];
#pragma unroll
            for (int nt = 0; nt < 4; nt++) {
                const uint32_t addr = st + 2 * A2_B +
                                      (uint32_t)(browL + nt * 16) * PITCH +
                                      (uint32_t)(kk * 2 + bChunk) * 16;
                LDMX4(bh[nt], addr);
                LDMX4(bl[nt], addr + B2_B);
            }
#pragma unroll
            for (int mt = 0; mt < 4; mt++)
#pragma unroll
                for (int nt = 0; nt < 4; nt++) {
                    MMA16816(acc[mt][2 * nt],     ah[mt], bh[nt][0], bh[nt][1]);
                    MMA16816(acc[mt][2 * nt],     ah[mt], bl[nt][0], bl[nt][1]);
                    MMA16816(acc[mt][2 * nt],     al[mt], bh[nt][0], bh[nt][1]);
                    MMA16816(acc[mt][2 * nt + 1], ah[mt], bh[nt][2], bh[nt][3]);
                    MMA16816(acc[mt][2 * nt + 1], ah[mt], bl[nt][2], bl[nt][3]);
                    MMA16816(acc[mt][2 * nt + 1], al[mt], bh[nt][2], bh[nt][3]);
                }
        }
        __syncthreads();
    }

    const int qrow = lane >> 2;
    const int qcol = (lane & 3) * 2;

    // stage 128x256 fp32 (128 KB), swizzle col ^ (row & 31)
    float* stage = (float*)sm;
    __syncthreads();
#pragma unroll
    for (int mt = 0; mt < 4; mt++) {
#pragma unroll
        for (int h = 0; h < 2; h++) {
            const int rl = wm * 64 + mt * 16 + qrow + h * 8;
#pragma unroll
            for (int n8 = 0; n8 < 8; n8++) {
                const int cl = wn * 64 + n8 * 8 + qcol;
                float v0 = acc[mt][n8][h * 2 + 0];
                float v1 = acc[mt][n8][h * 2 + 1];
                const size_t ao = (size_t)(bM + rl) * LD + bN + cl;
                __nv_bfloat162 a2 = *(const __nv_bfloat162*)(auxhi + ao);
                __nv_bfloat162 l2 = *(const __nv_bfloat162*)(auxlo + ao);
                v0 = fmaf(NSC_A, __bfloat162float(a2.x) + __bfloat162float(l2.x), v0);
                v1 = fmaf(NSC_A, __bfloat162float(a2.y) + __bfloat162float(l2.y), v1);
                stage[rl * 256 + (cl ^ (rl & 31))] = v0;
                stage[rl * 256 + ((cl + 1) ^ (rl & 31))] = v1;
            }
        }
    }
    __syncthreads();

    if (!LASTF16) {
        const int cb = lane * 2;
#pragma unroll 2
        for (int rr = 0; rr < 16; rr++) {
            const int r = wid * 16 + rr;
            const int rx = r & 31;
#pragma unroll
            for (int j = 0; j < 4; j++) {
                const int c = cb + 64 * j;
                float f0 = stage[r * 256 + (c ^ rx)];
                float f1 = stage[r * 256 + ((c + 1) ^ rx)];
                store_split2(Chi, Clo, (size_t)(bM + r) * LD + bN + c, f0, f1);
            }
        }
    }
    {
        const int cb = lane * 2;
#pragma unroll 2
        for (int rr = 0; rr < 32; rr++) {
            const int rp = wid * 32 + rr;
#pragma unroll
            for (int j = 0; j < 2; j++) {
                const int cp = cb + 64 * j;
                float f0 = stage[cp * 256 + (rp ^ (cp & 31))];
                float f1 = stage[(cp + 1) * 256 + (rp ^ ((cp + 1) & 31))];
                const size_t off = (size_t)(bN + rp) * LD + bM + cp;
                if (LASTF16)
                    store_split2h((__half*)Tp_hi, (__half*)Tp_lo, off, f0, f1);
                else
                    store_split2((__nv_bfloat16*)Tp_hi, (__nv_bfloat16*)Tp_lo, off, f0, f1);
            }
        }
    }
}

// ===== FINAL kernel: fp16, A single + B hi/lo (2 MMA products) ===============
// out = x16 @ WT^T + bias (fp32 out)
static constexpr int FSTG = A2_B + 2 * B2_B;             // 92160
static constexpr int SMEM_FIN = 2 * FSTG;                // 184320

__global__ __launch_bounds__(256, 1) void mmagemm_fin(
    const __half* __restrict__ A16,
    const __half* __restrict__ Bhi, const __half* __restrict__ Blo,
    const float* __restrict__ bias, float* __restrict__ Cf32) {
    extern __shared__ char sm[];
    const uint32_t smb = smem_u32(sm);
    const int tid = threadIdx.x;
    const int wid = tid >> 5;
    const int lane = tid & 31;
    const int bM = blockIdx.y * B2M;
    const int bN = blockIdx.x * B2N;

    // per chunk: A 128 rows x 8 q + B 256 rows x 8 q x 2 arrays = 5120 cpa16
    auto load_chunk = [&](int c, int s) {
        const uint32_t st = smb + s * FSTG;
#pragma unroll
        for (int it = 0; it < 20; it++) {
            const int idx = tid + it * 256;   // 0..5119
            if (idx < 1024) {
                const int row = idx >> 3;
                const int q = idx & 7;
                cpa16(st + row * PITCH + q * 16,
                      A16 + (size_t)(bM + row) * LD + c * B2K + q * 8);
            } else {
                const int j = idx - 1024;       // 0..4095
                const int row = j >> 4;         // 0..255
                const int q = (j >> 1) & 7;
                const int hl = j & 1;
                const uint32_t so = st + A2_B + hl * B2_B + row * PITCH + q * 16;
                const size_t g = (size_t)(bN + row) * LD + c * B2K + q * 8;
                cpa16(so, (hl ? Blo : Bhi) + g);
            }
        }
    };

    const int wm = wid & 1;
    const int wn = wid >> 1;
    const int arowL = wm * 64 + (lane & 15);
    const int aChunk = lane >> 4;
    const int browL = wn * 64 + (lane & 7) + ((lane >> 4) & 1) * 8;
    const int bChunk = (lane >> 3) & 1;

    float acc[4][8][4];
#pragma unroll
    for (int a = 0; a < 4; a++)
#pragma unroll
        for (int b = 0; b < 8; b++)
#pragma unroll
            for (int q = 0; q < 4; q++) acc[a][b][q] = 0.f;

    load_chunk(0, 0);
    CP_COMMIT();

#pragma unroll 1
    for (int c = 0; c < NC2; c++) {
        if (c + 1 < NC2) {
            load_chunk(c + 1, (c + 1) & 1);
            CP_COMMIT();
            CP_WAIT1();
        } else {
            CP_WAIT0();
        }
        __syncthreads();

        const uint32_t st = smb + (c & 1) * FSTG;
#pragma unroll
        for (int kk = 0; kk < 4; kk++) {
            uint32_t ah[4][4];
#pragma unroll
            for (int mt = 0; mt < 4; mt++) {
                const uint32_t addr = st + (uint32_t)(arowL + mt * 16) * PITCH +
                                      (uint32_t)(kk * 2 + aChunk) * 16;
                LDMX4(ah[mt], addr);
            }
            uint32_t bh[4][4], bl[4][4];
#pragma unroll
            for (int nt = 0; nt < 4; nt++) {
                const uint32_t addr = st + A2_B +
                                      (uint32_t)(browL + nt * 16) * PITCH +
                                      (uint32_t)(kk * 2 + bChunk) * 16;
                LDMX4(bh[nt], addr);
                LDMX4(bl[nt], addr + B2_B);
            }
#pragma unroll
            for (int mt = 0; mt < 4; mt++)
#pragma unroll
                for (int nt = 0; nt < 4; nt++) {
                    MMAH16816(acc[mt][2 * nt],     ah[mt], bh[nt][0], bh[nt][1]);
                    MMAH16816(acc[mt][2 * nt],     ah[mt], bl[nt][0], bl[nt][1]);
                    MMAH16816(acc[mt][2 * nt + 1], ah[mt], bh[nt][2], bh[nt][3]);
                    MMAH16816(acc[mt][2 * nt + 1], ah[mt], bl[nt][2], bl[nt][3]);
                }
        }
        __syncthreads();
    }

    const int qrow = lane >> 2;
    const int qcol = (lane & 3) * 2;
#pragma unroll
    for (int mt = 0; mt < 4; mt++) {
#pragma unroll
        for (int h = 0; h < 2; h++) {
            const int row = bM + wm * 64 + mt * 16 + qrow + h * 8;
            float* cr = Cf32 + (size_t)row * LD;
#pragma unroll
            for (int n8 = 0; n8 < 8; n8++) {
                const int col = bN + wn * 64 + n8 * 8 + qcol;
                float2 b2 = *(const float2*)(bias + col);
                float2 o;
                o.x = acc[mt][n8][h * 2 + 0] + b2.x;
                o.y = acc[mt][n8][h * 2 + 1] + b2.y;
                *(float2*)(cr + col) = o;
            }
        }
    }
}

// ---------------- launch -----------------------------------------------------
extern "C" void kernel_launch(void* const* d_in, const int* in_sizes, int n_in,
                              void* d_out, int out_size) {
    const float* x = nullptr;
    const float* w = nullptr;
    const float* bias = nullptr;
    int x_size = 0;
    for (int i = 0; i < n_in; i++) {
        const int sz = in_sizes[i];
        if (sz == DIM) bias = (const float*)d_in[i];
        else if (sz == DIM * DIM) w = (const float*)d_in[i];
        else { x = (const float*)d_in[i]; x_size = sz; }
    }
    const int B_rows = x_size / DIM;  // 16384
    float* out = (float*)d_out;

    __nv_bfloat16 *pXhi[2], *pXlo[2], *pXThi[2], *pXTlo[2];
    __nv_bfloat16 *pGhi, *pGlo, *pBhi, *pBlo;
    __half *px16, *pWTh, *pWTl;
    {
        __nv_bfloat16* base;
        cudaGetSymbolAddress((void**)&base, g_Xhi);
        pXhi[0] = base; pXhi[1] = base + DIM * DIM;
        cudaGetSymbolAddress((void**)&base, g_Xlo);
        pXlo[0] = base; pXlo[1] = base + DIM * DIM;
        cudaGetSymbolAddress((void**)&base, g_XThi);
        pXThi[0] = base; pXThi[1] = base + DIM * DIM;
        cudaGetSymbolAddress((void**)&base, g_XTlo);
        pXTlo[0] = base; pXTlo[1] = base + DIM * DIM;
    }
    cudaGetSymbolAddress((void**)&pGhi, g_Ghi);
    cudaGetSymbolAddress((void**)&pGlo, g_Glo);
    cudaGetSymbolAddress((void**)&pBhi, g_Bhi);
    cudaGetSymbolAddress((void**)&pBlo, g_Blo);
    cudaGetSymbolAddress((void**)&px16, g_x16);
    cudaGetSymbolAddress((void**)&pWTh, g_WTh16);
    cudaGetSymbolAddress((void**)&pWTl, g_WTl16);

    cudaFuncSetAttribute(mmagemm_tri<0>, cudaFuncAttributeMaxDynamicSharedMemorySize, SMEM_TRI);
    cudaFuncSetAttribute(mmagemm_tri<1>, cudaFuncAttributeMaxDynamicSharedMemorySize, SMEM_TRI);
    cudaFuncSetAttribute(mmagemm_big<0>, cudaFuncAttributeMaxDynamicSharedMemorySize, SMEM_BIG);
    cudaFuncSetAttribute(mmagemm_big<1>, cudaFuncAttributeMaxDynamicSharedMemorySize, SMEM_BIG);
    cudaFuncSetAttribute(mmagemm_fin, cudaFuncAttributeMaxDynamicSharedMemorySize, SMEM_FIN);

    const int n = DIM * DIM;
    norm_partial_kernel<<<256, 256>>>(w, n);
    norm_finalize_kernel<<<1, 256>>>();
    scale_split_trans_kernel<<<dim3(64, 64), dim3(32, 8)>>>(
        w, pXhi[0], pXlo[0], pXThi[0], pXTlo[0]);
    cvt16_kernel<<<4096, 256>>>((const float4*)x, (__half2*)px16, B_rows * DIM / 4);

    const int NT = 16;
    dim3 gtri(NT * (NT + 1) / 2, 1);         // 136 CTAs
    dim3 g2(DIM / B2N, DIM / B2M);           // (8, 16) = 128 CTAs
    for (int s = 0; s < 10; s++) {
        const int c0 = s & 1, n1 = c0 ^ 1;
        // G = X @ X^T (symmetric, triangular + mirror)
        mmagemm_tri<0><<<gtri, 256, SMEM_TRI>>>(
            pXhi[c0], pXlo[c0], pXhi[c0], pXlo[c0],
            nullptr, nullptr, pGhi, pGlo);
        // Bm = c*(G@G) + b*G (symmetric, triangular + mirror)
        mmagemm_tri<1><<<gtri, 256, SMEM_TRI>>>(
            pGhi, pGlo, pGhi, pGlo,
            pGhi, pGlo, pBhi, pBlo);
        // X' = Bm@X + a*X
        if (s < 9) {
            mmagemm_big<0><<<g2, 256, SMEM_BIG>>>(
                pBhi, pBlo, pXThi[c0], pXTlo[c0],
                pXhi[c0], pXlo[c0],
                pXhi[n1], pXlo[n1], pXThi[n1], pXTlo[n1]);
        } else {
            // last step: transposed output straight to fp16 split for final GEMM
            mmagemm_big<1><<<g2, 256, SMEM_BIG>>>(
                pBhi, pBlo, pXThi[c0], pXTlo[c0],
                pXhi[c0], pXlo[c0],
                nullptr, nullptr, pWTh, pWTl);
        }
    }
    // out = x16 @ Wfinal^T(fp16 hi/lo) + bias
    dim3 gout(DIM / B2N, B_rows / B2M);  // (8, 128)
    mmagemm_fin<<<gout, 256, SMEM_FIN>>>(px16, pWTh, pWTl, bias, out);
}

// round 12
// speedup vs baseline: 1.2984x; 1.0818x over previous
#include <cuda_runtime.h>
#include <cuda_bf16.h>
#include <cuda_fp16.h>
#include <cstdint>
#include <math.h>

static constexpr int DIM = 2048;
static constexpr int LD = 2048;
static constexpr float NSC_A = 3.4445f;
static constexpr float NSC_B = -4.7750f;
static constexpr float NSC_C = 2.0315f;

// ---------------- scratch (allocation-free: __device__ globals) -------------
__device__ __align__(256) __nv_bfloat16 g_Xhi [2][DIM * DIM];
__device__ __align__(256) __nv_bfloat16 g_Xlo [2][DIM * DIM];
__device__ __align__(256) __nv_bfloat16 g_XThi[2][DIM * DIM];
__device__ __align__(256) __nv_bfloat16 g_XTlo[2][DIM * DIM];
__device__ __align__(256) __nv_bfloat16 g_Ghi [DIM * DIM];
__device__ __align__(256) __nv_bfloat16 g_Glo [DIM * DIM];
__device__ __align__(256) __nv_bfloat16 g_Bhi [DIM * DIM];
__device__ __align__(256) __nv_bfloat16 g_Blo [DIM * DIM];
__device__ __align__(256) __half g_x16[16384 * DIM];
__device__ __align__(256) __half g_WT16[DIM * DIM];
__device__ float g_partial[256];
__device__ float g_scale;

// ---------------- helpers ----------------------------------------------------
__device__ __forceinline__ uint32_t smem_u32(const void* p) {
    uint32_t a;
    asm("{ .reg .u64 t; cvta.to.shared.u64 t, %1; cvt.u32.u64 %0, t; }" : "=r"(a) : "l"(p));
    return a;
}
__device__ __forceinline__ void cpa16(uint32_t dst, const void* src) {
    asm volatile("cp.async.cg.shared.global [%0], [%1], 16;" :: "r"(dst), "l"(src) : "memory");
}
#define CP_COMMIT() asm volatile("cp.async.commit_group;" ::: "memory")
#define CP_WAIT1()  asm volatile("cp.async.wait_group 1;" ::: "memory")
#define CP_WAIT0()  asm volatile("cp.async.wait_group 0;" ::: "memory")
#define BARG(id)    asm volatile("bar.sync %0, 128;" :: "r"(id) : "memory")

#define LDMX4(r, a)                                                              \
    asm volatile("ldmatrix.sync.aligned.m8n8.x4.shared.b16 {%0,%1,%2,%3}, [%4];" \
        : "=r"((r)[0]), "=r"((r)[1]), "=r"((r)[2]), "=r"((r)[3]) : "r"(a))

#define MMA16816(acc, a, b0, b1)                                                  \
    asm volatile("mma.sync.aligned.m16n8k16.row.col.f32.bf16.bf16.f32 "           \
        "{%0,%1,%2,%3}, {%4,%5,%6,%7}, {%8,%9}, {%0,%1,%2,%3};"                   \
        : "+f"((acc)[0]), "+f"((acc)[1]), "+f"((acc)[2]), "+f"((acc)[3])          \
        : "r"((a)[0]), "r"((a)[1]), "r"((a)[2]), "r"((a)[3]), "r"(b0), "r"(b1))

#define MMAH16816(acc, a, b0, b1)                                                 \
    asm volatile("mma.sync.aligned.m16n8k16.row.col.f32.f16.f16.f32 "             \
        "{%0,%1,%2,%3}, {%4,%5,%6,%7}, {%8,%9}, {%0,%1,%2,%3};"                   \
        : "+f"((acc)[0]), "+f"((acc)[1]), "+f"((acc)[2]), "+f"((acc)[3])          \
        : "r"((a)[0]), "r"((a)[1]), "r"((a)[2]), "r"((a)[3]), "r"(b0), "r"(b1))

__device__ __forceinline__ void store_split4(__nv_bfloat16* H, __nv_bfloat16* L, size_t off,
                                             float f0, float f1, float f2, float f3) {
    __nv_bfloat16 h0 = __float2bfloat16(f0), h1 = __float2bfloat16(f1);
    __nv_bfloat16 h2 = __float2bfloat16(f2), h3 = __float2bfloat16(f3);
    __nv_bfloat162 hA, hB, lA, lB;
    hA.x = h0; hA.y = h1; hB.x = h2; hB.y = h3;
    lA.x = __float2bfloat16(f0 - __bfloat162float(h0));
    lA.y = __float2bfloat16(f1 - __bfloat162float(h1));
    lB.x = __float2bfloat16(f2 - __bfloat162float(h2));
    lB.y = __float2bfloat16(f3 - __bfloat162float(h3));
    *(__nv_bfloat162*)(H + off) = hA;
    *(__nv_bfloat162*)(H + off + 2) = hB;
    *(__nv_bfloat162*)(L + off) = lA;
    *(__nv_bfloat162*)(L + off + 2) = lB;
}
__device__ __forceinline__ void store_split2(__nv_bfloat16* H, __nv_bfloat16* L, size_t off,
                                             float f0, float f1) {
    __nv_bfloat16 h0 = __float2bfloat16(f0), h1 = __float2bfloat16(f1);
    __nv_bfloat162 h2, l2;
    h2.x = h0; h2.y = h1;
    l2.x = __float2bfloat16(f0 - __bfloat162float(h0));
    l2.y = __float2bfloat16(f1 - __bfloat162float(h1));
    *(__nv_bfloat162*)(H + off) = h2;
    *(__nv_bfloat162*)(L + off) = l2;
}

// ---------------- small kernels ---------------------------------------------
__global__ void norm_partial_kernel(const float* __restrict__ w, int n) {
    __shared__ float sd[256];
    float s = 0.f;
    for (int i = blockIdx.x * blockDim.x + threadIdx.x; i < n; i += gridDim.x * blockDim.x) {
        float v = w[i];
        s = fmaf(v, v, s);
    }
    sd[threadIdx.x] = s;
    __syncthreads();
    for (int o = 128; o; o >>= 1) {
        if (threadIdx.x < o) sd[threadIdx.x] += sd[threadIdx.x + o];
        __syncthreads();
    }
    if (threadIdx.x == 0) g_partial[blockIdx.x] = sd[0];
}
__global__ void norm_finalize_kernel() {
    __shared__ float sd[256];
    sd[threadIdx.x] = g_partial[threadIdx.x];
    __syncthreads();
    for (int o = 128; o; o >>= 1) {
        if (threadIdx.x < o) sd[threadIdx.x] += sd[threadIdx.x + o];
        __syncthreads();
    }
    if (threadIdx.x == 0) g_scale = 1.0f / (sqrtf(sd[0]) + 1e-7f);
}
// fp32 -> single fp16 convert, float4 vectorized
__global__ void cvt16_kernel(const float4* __restrict__ s, __half2* __restrict__ o, int n4) {
    for (int i = blockIdx.x * blockDim.x + threadIdx.x; i < n4; i += gridDim.x * blockDim.x) {
        float4 v = s[i];
        __half2 a, b;
        a.x = __float2half_rn(v.x); a.y = __float2half_rn(v.y);
        b.x = __float2half_rn(v.z); b.y = __float2half_rn(v.w);
        o[2 * i] = a;
        o[2 * i + 1] = b;
    }
}
// fused: scale + split (normal) + transposed split, one pass over w
__global__ void scale_split_trans_kernel(const float* __restrict__ w,
                                         __nv_bfloat16* __restrict__ hi, __nv_bfloat16* __restrict__ lo,
                                         __nv_bfloat16* __restrict__ thi, __nv_bfloat16* __restrict__ tlo) {
    __shared__ float t[32][33];
    const float s = g_scale;
    int x = blockIdx.x * 32 + threadIdx.x;
    int y0 = blockIdx.y * 32;
    for (int j = threadIdx.y; j < 32; j += 8) {
        float v = w[(size_t)(y0 + j) * LD + x] * s;
        t[j][threadIdx.x] = v;
        size_t o = (size_t)(y0 + j) * LD + x;
        __nv_bfloat16 h = __float2bfloat16(v);
        hi[o] = h;
        lo[o] = __float2bfloat16(v - __bfloat162float(h));
    }
    __syncthreads();
    int ox = blockIdx.y * 32 + threadIdx.x;
    for (int j = threadIdx.y; j < 32; j += 8) {
        float v = t[threadIdx.x][j];
        size_t o = (size_t)(blockIdx.x * 32 + j) * LD + ox;
        __nv_bfloat16 h = __float2bfloat16(v);
        thi[o] = h;
        tlo[o] = __float2bfloat16(v - __bfloat162float(h));
    }
}

// ====== TRIANGULAR kernel (modes 0/1): two INDEPENDENT split-K groups ========
static constexpr int TK = 32;
static constexpr int NCK = 1024 / TK;          // 32 chunks per group
static constexpr int TPITCH = 80;
static constexpr int TAT = 128 * TPITCH;       // 10240
static constexpr int TSTG = 4 * TAT;           // 40960
static constexpr int TGRP = 2 * TSTG;          // 81920
static constexpr int SMEM_TRI = 2 * TGRP;      // 163840

template <int MODE>
__global__ __launch_bounds__(256, 1) void mmagemm_tri(
    const __nv_bfloat16* __restrict__ Ahi, const __nv_bfloat16* __restrict__ Alo,
    const __nv_bfloat16* __restrict__ Bhi, const __nv_bfloat16* __restrict__ Blo,
    const __nv_bfloat16* __restrict__ auxhi, const __nv_bfloat16* __restrict__ auxlo,
    __nv_bfloat16* __restrict__ Chi, __nv_bfloat16* __restrict__ Clo) {
    extern __shared__ char sm[];
    const uint32_t smb = smem_u32(sm);
    const int tid = threadIdx.x;
    const int wid = tid >> 5;
    const int lane = tid & 31;
    const int g = tid >> 7;
    const int tg = tid & 127;
    const int wig = (tid >> 5) & 3;
    const int barid = 1 + g;

    const int i = blockIdx.x;
    float fq = sqrtf(8.0f * (float)i + 1.0f);
    int tn = (int)((fq - 1.0f) * 0.5f);
    while ((tn + 1) * (tn + 2) / 2 <= i) tn++;
    while (tn * (tn + 1) / 2 > i) tn--;
    int tm = i - tn * (tn + 1) / 2;
    const int bM = tm * 128;
    const int bN = tn * 128;

    const uint32_t gbase = smb + g * TGRP;
    const int kbase = g * 1024;

    auto load_chunk = [&](int c, int s) {
        const uint32_t st = gbase + s * TSTG;
        const int e0 = kbase + c * TK;
#pragma unroll
        for (int it = 0; it < 8; it++) {
            const int idx = tg + it * 128;
            const int row = idx >> 3;
            const int q = (idx >> 1) & 3;
            const int ab = idx & 1;
            const uint32_t so = st + ab * (2 * TAT) + row * TPITCH + q * 16;
            const size_t gg = (size_t)((ab ? bN : bM) + row) * LD + e0 + q * 8;
            cpa16(so, (ab ? Bhi : Ahi) + gg);
            cpa16(so + TAT, (ab ? Blo : Alo) + gg);
        }
    };

    const int wm = wig & 1;
    const int wn = wig >> 1;
    const int arowL = wm * 64 + (lane & 15);
    const int aChunk = lane >> 4;
    const int browL = wn * 64 + (lane & 7) + ((lane >> 4) & 1) * 8;
    const int bChunk = (lane >> 3) & 1;

    float acc[4][8][4];
#pragma unroll
    for (int a = 0; a < 4; a++)
#pragma unroll
        for (int b = 0; b < 8; b++)
#pragma unroll
            for (int q = 0; q < 4; q++) acc[a][b][q] = 0.f;

    load_chunk(0, 0);
    CP_COMMIT();

#pragma unroll 1
    for (int c = 0; c < NCK; c++) {
        if (c + 1 < NCK) {
            load_chunk(c + 1, (c + 1) & 1);
            CP_COMMIT();
            CP_WAIT1();
        } else {
            CP_WAIT0();
        }
        BARG(barid);

        const uint32_t st = gbase + (c & 1) * TSTG;
#pragma unroll
        for (int kk = 0; kk < 2; kk++) {
            uint32_t ah[4][4], al[4][4];
#pragma unroll
            for (int mt = 0; mt < 4; mt++) {
                const uint32_t addr = st + (uint32_t)(arowL + mt * 16) * TPITCH +
                                      (uint32_t)(kk * 2 + aChunk) * 16;
                LDMX4(ah[mt], addr);
                LDMX4(al[mt], addr + TAT);
            }
            uint32_t bh[4][4], bl[4][4];
#pragma unroll
            for (int nt = 0; nt < 4; nt++) {
                const uint32_t addr = st + 2 * TAT +
                                      (uint32_t)(browL + nt * 16) * TPITCH +
                                      (uint32_t)(kk * 2 + bChunk) * 16;
                LDMX4(bh[nt], addr);
                LDMX4(bl[nt], addr + TAT);
            }
#pragma unroll
            for (int mt = 0; mt < 4; mt++)
#pragma unroll
                for (int nt = 0; nt < 4; nt++) {
                    MMA16816(acc[mt][2 * nt],     ah[mt], bh[nt][0], bh[nt][1]);
                    MMA16816(acc[mt][2 * nt],     ah[mt], bl[nt][0], bl[nt][1]);
                    MMA16816(acc[mt][2 * nt],     al[mt], bh[nt][0], bh[nt][1]);
                    MMA16816(acc[mt][2 * nt + 1], ah[mt], bh[nt][2], bh[nt][3]);
                    MMA16816(acc[mt][2 * nt + 1], ah[mt], bl[nt][2], bl[nt][3]);
                    MMA16816(acc[mt][2 * nt + 1], al[mt], bh[nt][2], bh[nt][3]);
                }
        }
        BARG(barid);
    }

    // ---- cross-group reduction through fp32 stage ---------------------------
    const int qrow = lane >> 2;
    const int qcol = (lane & 3) * 2;
    float* stage = (float*)sm;
    __syncthreads();
    if (g == 0) {
#pragma unroll
        for (int mt = 0; mt < 4; mt++)
#pragma unroll
            for (int h = 0; h < 2; h++) {
                const int rl = wm * 64 + mt * 16 + qrow + h * 8;
#pragma unroll
                for (int n8 = 0; n8 < 8; n8++) {
                    const int cl = wn * 64 + n8 * 8 + qcol;
                    stage[rl * 128 + (cl ^ (rl & 31))] = acc[mt][n8][h * 2 + 0];
                    stage[rl * 128 + ((cl + 1) ^ (rl & 31))] = acc[mt][n8][h * 2 + 1];
                }
            }
    }
    __syncthreads();
    if (g == 1) {
#pragma unroll
        for (int mt = 0; mt < 4; mt++)
#pragma unroll
            for (int h = 0; h < 2; h++) {
                const int rl = wm * 64 + mt * 16 + qrow + h * 8;
#pragma unroll
                for (int n8 = 0; n8 < 8; n8++) {
                    const int cl = wn * 64 + n8 * 8 + qcol;
                    const int s0 = rl * 128 + (cl ^ (rl & 31));
                    const int s1 = rl * 128 + ((cl + 1) ^ (rl & 31));
                    float v0 = stage[s0] + acc[mt][n8][h * 2 + 0];
                    float v1 = stage[s1] + acc[mt][n8][h * 2 + 1];
                    if (MODE == 1) {
                        const size_t ao = (size_t)(bM + rl) * LD + bN + cl;
                        __nv_bfloat162 a2 = *(const __nv_bfloat162*)(auxhi + ao);
                        __nv_bfloat162 l2 = *(const __nv_bfloat162*)(auxlo + ao);
                        v0 = NSC_C * v0 + NSC_B * (__bfloat162float(a2.x) + __bfloat162float(l2.x));
                        v1 = NSC_C * v1 + NSC_B * (__bfloat162float(a2.y) + __bfloat162float(l2.y));
                    }
                    stage[s0] = v0;
                    stage[s1] = v1;
                }
            }
    }
    __syncthreads();

    const int c4 = lane * 4;
#pragma unroll 4
    for (int rr = 0; rr < 16; rr++) {
        const int r = wid * 16 + rr;
        const int rx = r & 31;
        float f0 = stage[r * 128 + ((c4 + 0) ^ rx)];
        float f1 = stage[r * 128 + ((c4 + 1) ^ rx)];
        float f2 = stage[r * 128 + ((c4 + 2) ^ rx)];
        float f3 = stage[r * 128 + ((c4 + 3) ^ rx)];
        store_split4(Chi, Clo, (size_t)(bM + r) * LD + bN + c4, f0, f1, f2, f3);
    }
    if (tm != tn) {
#pragma unroll 4
        for (int rr = 0; rr < 16; rr++) {
            const int r = wid * 16 + rr;
            float f0 = stage[(c4 + 0) * 128 + (r ^ ((c4 + 0) & 31))];
            float f1 = stage[(c4 + 1) * 128 + (r ^ ((c4 + 1) & 31))];
            float f2 = stage[(c4 + 2) * 128 + (r ^ ((c4 + 2) & 31))];
            float f3 = stage[(c4 + 3) * 128 + (r ^ ((c4 + 3) & 31))];
            store_split4(Chi, Clo, (size_t)(bN + r) * LD + bM + c4, f0, f1, f2, f3);
        }
    }
}

// ===== BIG kernel (mode 2): CTA 128x256, 64x64 warp tile, BK=64 2-stage ======
// LASTF16=0: writes split bf16 C + transposed split bf16 T (NS loop)
// LASTF16=1: skips C; writes transposed SINGLE fp16 T (feeds final fp16 GEMM)
static constexpr int B2M = 128, B2N = 256, B2K = 64;
static constexpr int NC2 = DIM / B2K;                    // 32 chunks
static constexpr int PITCH = 144;
static constexpr int A2_B = B2M * PITCH;                 // 18432
static constexpr int B2_B = B2N * PITCH;                 // 36864
static constexpr int STG2 = 2 * A2_B + 2 * B2_B;         // 110592
static constexpr int SMEM_BIG = 2 * STG2;                // 221184

template <int LASTF16>
__global__ __launch_bounds__(256, 1) void mmagemm_big(
    const __nv_bfloat16* __restrict__ Ahi, const __nv_bfloat16* __restrict__ Alo,
    const __nv_bfloat16* __restrict__ Bhi, const __nv_bfloat16* __restrict__ Blo,
    const __nv_bfloat16* __restrict__ auxhi, const __nv_bfloat16* __restrict__ auxlo,
    __nv_bfloat16* __restrict__ Chi, __nv_bfloat16* __restrict__ Clo,
    void* __restrict__ Tp_hi, void* __restrict__ Tp_lo) {
    extern __shared__ char sm[];
    const uint32_t smb = smem_u32(sm);
    const int tid = threadIdx.x;
    const int wid = tid >> 5;
    const int lane = tid & 31;
    const int bM = blockIdx.y * B2M;
    const int bN = blockIdx.x * B2N;

    auto load_chunk = [&](int c, int s) {
        const uint32_t st = smb + s * STG2;
#pragma unroll
        for (int it = 0; it < 12; it++) {
            const int i = tid + it * 256;
            const int row = i >> 3;
            const int q = i & 7;
            if (row < B2M) {
                const size_t g = (size_t)(bM + row) * LD + c * B2K + q * 8;
                const uint32_t so = st + row * PITCH + q * 16;
                cpa16(so, Ahi + g);
                cpa16(so + A2_B, Alo + g);
            } else {
                const int br = row - B2M;
                const size_t g = (size_t)(bN + br) * LD + c * B2K + q * 8;
                const uint32_t so = st + 2 * A2_B + br * PITCH + q * 16;
                cpa16(so, Bhi + g);
                cpa16(so + B2_B, Blo + g);
            }
        }
    };

    const int wm = wid & 1;
    const int wn = wid >> 1;
    const int arowL = wm * 64 + (lane & 15);
    const int aChunk = lane >> 4;
    const int browL = wn * 64 + (lane & 7) + ((lane >> 4) & 1) * 8;
    const int bChunk = (lane >> 3) & 1;

    float acc[4][8][4];
#pragma unroll
    for (int a = 0; a < 4; a++)
#pragma unroll
        for (int b = 0; b < 8; b++)
#pragma unroll
            for (int q = 0; q < 4; q++) acc[a][b][q] = 0.f;

    load_chunk(0, 0);
    CP_COMMIT();

#pragma unroll 1
    for (int c = 0; c < NC2; c++) {
        if (c + 1 < NC2) {
            load_chunk(c + 1, (c + 1) & 1);
            CP_COMMIT();
            CP_WAIT1();
        } else {
            CP_WAIT0();
        }
        __syncthreads();

        const uint32_t st = smb + (c & 1) * STG2;
#pragma unroll
        for (int kk = 0; kk < 4; kk++) {
            uint32_t ah[4][4], al[4][4];
#pragma unroll
            for (int mt = 0; mt < 4; mt++) {
                const uint32_t addr = st + (uint32_t)(arowL + mt * 16) * PITCH +
                                      (uint32_t)(kk * 2 + aChunk) * 16;
                LDMX4(ah[mt], addr);
                LDMX4(al[mt], addr + A2_B);
            }
            uint32_t bh[4][4], bl[4][4];
#pragma unroll
            for (int nt = 0; nt < 4; nt++) {
                const uint32_t addr = st + 2 * A2_B +
                                      (uint32_t)(browL + nt * 16) * PITCH +
                                      (uint32_t)(kk * 2 + bChunk) * 16;
                LDMX4(bh[nt], addr);
                LDMX4(bl[nt], addr + B2_B);
            }
#pragma unroll
            for (int mt = 0; mt < 4; mt++)
#pragma unroll
                for (int nt = 0; nt < 4; nt++) {
                    MMA16816(acc[mt][2 * nt],     ah[mt], bh[nt][0], bh[nt][1]);
                    MMA16816(acc[mt][2 * nt],     ah[mt], bl[nt][0], bl[nt][1]);
                    MMA16816(acc[mt][2 * nt],     al[mt], bh[nt][0], bh[nt][1]);
                    MMA16816(acc[mt][2 * nt + 1], ah[mt], bh[nt][2], bh[nt][3]);
                    MMA16816(acc[mt][2 * nt + 1], ah[mt], bl[nt][2], bl[nt][3]);
                    MMA16816(acc[mt][2 * nt + 1], al[mt], bh[nt][2], bh[nt][3]);
                }
        }
        __syncthreads();
    }

    const int qrow = lane >> 2;
    const int qcol = (lane & 3) * 2;

    // stage 128x256 fp32 (128 KB), swizzle col ^ (row & 31)
    float* stage = (float*)sm;
    __syncthreads();
#pragma unroll
    for (int mt = 0; mt < 4; mt++) {
#pragma unroll
        for (int h = 0; h < 2; h++) {
            const int rl = wm * 64 + mt * 16 + qrow + h * 8;
#pragma unroll
            for (int n8 = 0; n8 < 8; n8++) {
                const int cl = wn * 64 + n8 * 8 + qcol;
                float v0 = acc[mt][n8][h * 2 + 0];
                float v1 = acc[mt][n8][h * 2 + 1];
                const size_t ao = (size_t)(bM + rl) * LD + bN + cl;
                __nv_bfloat162 a2 = *(const __nv_bfloat162*)(auxhi + ao);
                __nv_bfloat162 l2 = *(const __nv_bfloat162*)(auxlo + ao);
                v0 = fmaf(NSC_A, __bfloat162float(a2.x) + __bfloat162float(l2.x), v0);
                v1 = fmaf(NSC_A, __bfloat162float(a2.y) + __bfloat162float(l2.y), v1);
                stage[rl * 256 + (cl ^ (rl & 31))] = v0;
                stage[rl * 256 + ((cl + 1) ^ (rl & 31))] = v1;
            }
        }
    }
    __syncthreads();

    if (!LASTF16) {
        const int cb = lane * 2;
#pragma unroll 2
        for (int rr = 0; rr < 16; rr++) {
            const int r = wid * 16 + rr;
            const int rx = r & 31;
#pragma unroll
            for (int j = 0; j < 4; j++) {
                const int c = cb + 64 * j;
                float f0 = stage[r * 256 + (c ^ rx)];
                float f1 = stage[r * 256 + ((c + 1) ^ rx)];
                store_split2(Chi, Clo, (size_t)(bM + r) * LD + bN + c, f0, f1);
            }
        }
    }
    {
        const int cb = lane * 2;
#pragma unroll 2
        for (int rr = 0; rr < 32; rr++) {
            const int rp = wid * 32 + rr;
#pragma unroll
            for (int j = 0; j < 2; j++) {
                const int cp = cb + 64 * j;
                float f0 = stage[cp * 256 + (rp ^ (cp & 31))];
                float f1 = stage[(cp + 1) * 256 + (rp ^ ((cp + 1) & 31))];
                const size_t off = (size_t)(bN + rp) * LD + bM + cp;
                if (LASTF16) {
                    __half2 h2;
                    h2.x = __float2half_rn(f0);
                    h2.y = __float2half_rn(f1);
                    *(__half2*)((__half*)Tp_hi + off) = h2;
                } else {
                    store_split2((__nv_bfloat16*)Tp_hi, (__nv_bfloat16*)Tp_lo, off, f0, f1);
                }
            }
        }
    }
}

// ===== FINAL kernel: fp16 single x single (1 MMA product) ====================
// out = x16 @ WT^T + bias (fp32 out)
static constexpr int FSTG = A2_B + B2_B;                 // 55296
static constexpr int SMEM_FIN = 2 * FSTG;                // 110592

__global__ __launch_bounds__(256, 1) void mmagemm_fin(
    const __half* __restrict__ A16, const __half* __restrict__ B16,
    const float* __restrict__ bias, float* __restrict__ Cf32) {
    extern __shared__ char sm[];
    const uint32_t smb = smem_u32(sm);
    const int tid = threadIdx.x;
    const int wid = tid >> 5;
    const int lane = tid & 31;
    const int bM = blockIdx.y * B2M;
    const int bN = blockIdx.x * B2N;

    // per chunk: A 128 rows x 8 q + B 256 rows x 8 q = 3072 cpa16
    auto load_chunk = [&](int c, int s) {
        const uint32_t st = smb + s * FSTG;
#pragma unroll
        for (int it = 0; it < 12; it++) {
            const int idx = tid + it * 256;   // 0..3071
            if (idx < 1024) {
                const int row = idx >> 3;
                const int q = idx & 7;
                cpa16(st + row * PITCH + q * 16,
                      A16 + (size_t)(bM + row) * LD + c * B2K + q * 8);
            } else {
                const int j = idx - 1024;       // 0..2047
                const int row = j >> 3;         // 0..255
                const int q = j & 7;
                cpa16(st + A2_B + row * PITCH + q * 16,
                      B16 + (size_t)(bN + row) * LD + c * B2K + q * 8);
            }
        }
    };

    const int wm = wid & 1;
    const int wn = wid >> 1;
    const int arowL = wm * 64 + (lane & 15);
    const int aChunk = lane >> 4;
    const int browL = wn * 64 + (lane & 7) + ((lane >> 4) & 1) * 8;
    const int bChunk = (lane >> 3) & 1;

    float acc[4][8][4];
#pragma unroll
    for (int a = 0; a < 4; a++)
#pragma unroll
        for (int b = 0; b < 8; b++)
#pragma unroll
            for (int q = 0; q < 4; q++) acc[a][b][q] = 0.f;

    load_chunk(0, 0);
    CP_COMMIT();

#pragma unroll 1
    for (int c = 0; c < NC2; c++) {
        if (c + 1 < NC2) {
            load_chunk(c + 1, (c + 1) & 1);
            CP_COMMIT();
            CP_WAIT1();
        } else {
            CP_WAIT0();
        }
        __syncthreads();

        const uint32_t st = smb + (c & 1) * FSTG;
#pragma unroll
        for (int kk = 0; kk < 4; kk++) {
            uint32_t ah[4][4];
#pragma unroll
            for (int mt = 0; mt < 4; mt++) {
                const uint32_t addr = st + (uint32_t)(arowL + mt * 16) * PITCH +
                                      (uint32_t)(kk * 2 + aChunk) * 16;
                LDMX4(ah[mt], addr);
            }
            uint32_t bh[4][4];
#pragma unroll
            for (int nt = 0; nt < 4; nt++) {
                const uint32_t addr = st + A2_B +
                                      (uint32_t)(browL + nt * 16) * PITCH +
                                      (uint32_t)(kk * 2 + bChunk) * 16;
                LDMX4(bh[nt], addr);
            }
#pragma unroll
            for (int mt = 0; mt < 4; mt++)
#pragma unroll
                for (int nt = 0; nt < 4; nt++) {
                    MMAH16816(acc[mt][2 * nt],     ah[mt], bh[nt][0], bh[nt][1]);
                    MMAH16816(acc[mt][2 * nt + 1], ah[mt], bh[nt][2], bh[nt][3]);
                }
        }
        __syncthreads();
    }

    const int qrow = lane >> 2;
    const int qcol = (lane & 3) * 2;
#pragma unroll
    for (int mt = 0; mt < 4; mt++) {
#pragma unroll
        for (int h = 0; h < 2; h++) {
            const int row = bM + wm * 64 + mt * 16 + qrow + h * 8;
            float* cr = Cf32 + (size_t)row * LD;
#pragma unroll
            for (int n8 = 0; n8 < 8; n8++) {
                const int col = bN + wn * 64 + n8 * 8 + qcol;
                float2 b2 = *(const float2*)(bias + col);
                float2 o;
                o.x = acc[mt][n8][h * 2 + 0] + b2.x;
                o.y = acc[mt][n8][h * 2 + 1] + b2.y;
                *(float2*)(cr + col) = o;
            }
        }
    }
}

// ---------------- launch -----------------------------------------------------
extern "C" void kernel_launch(void* const* d_in, const int* in_sizes, int n_in,
                              void* d_out, int out_size) {
    const float* x = nullptr;
    const float* w = nullptr;
    const float* bias = nullptr;
    int x_size = 0;
    for (int i = 0; i < n_in; i++) {
        const int sz = in_sizes[i];
        if (sz == DIM) bias = (const float*)d_in[i];
        else if (sz == DIM * DIM) w = (const float*)d_in[i];
        else { x = (const float*)d_in[i]; x_size = sz; }
    }
    const int B_rows = x_size / DIM;  // 16384
    float* out = (float*)d_out;

    __nv_bfloat16 *pXhi[2], *pXlo[2], *pXThi[2], *pXTlo[2];
    __nv_bfloat16 *pGhi, *pGlo, *pBhi, *pBlo;
    __half *px16, *pWT;
    {
        __nv_bfloat16* base;
        cudaGetSymbolAddress((void**)&base, g_Xhi);
        pXhi[0] = base; pXhi[1] = base + DIM * DIM;
        cudaGetSymbolAddress((void**)&base, g_Xlo);
        pXlo[0] = base; pXlo[1] = base + DIM * DIM;
        cudaGetSymbolAddress((void**)&base, g_XThi);
        pXThi[0] = base; pXThi[1] = base + DIM * DIM;
        cudaGetSymbolAddress((void**)&base, g_XTlo);
        pXTlo[0] = base; pXTlo[1] = base + DIM * DIM;
    }
    cudaGetSymbolAddress((void**)&pGhi, g_Ghi);
    cudaGetSymbolAddress((void**)&pGlo, g_Glo);
    cudaGetSymbolAddress((void**)&pBhi, g_Bhi);
    cudaGetSymbolAddress((void**)&pBlo, g_Blo);
    cudaGetSymbolAddress((void**)&px16, g_x16);
    cudaGetSymbolAddress((void**)&pWT, g_WT16);

    cudaFuncSetAttribute(mmagemm_tri<0>, cudaFuncAttributeMaxDynamicSharedMemorySize, SMEM_TRI);
    cudaFuncSetAttribute(mmagemm_tri<1>, cudaFuncAttributeMaxDynamicSharedMemorySize, SMEM_TRI);
    cudaFuncSetAttribute(mmagemm_big<0>, cudaFuncAttributeMaxDynamicSharedMemorySize, SMEM_BIG);
    cudaFuncSetAttribute(mmagemm_big<1>, cudaFuncAttributeMaxDynamicSharedMemorySize, SMEM_BIG);
    cudaFuncSetAttribute(mmagemm_fin, cudaFuncAttributeMaxDynamicSharedMemorySize, SMEM_FIN);

    const int n = DIM * DIM;
    norm_partial_kernel<<<256, 256>>>(w, n);
    norm_finalize_kernel<<<1, 256>>>();
    scale_split_trans_kernel<<<dim3(64, 64), dim3(32, 8)>>>(
        w, pXhi[0], pXlo[0], pXThi[0], pXTlo[0]);
    cvt16_kernel<<<4096, 256>>>((const float4*)x, (__half2*)px16, B_rows * DIM / 4);

    const int NT = 16;
    dim3 gtri(NT * (NT + 1) / 2, 1);         // 136 CTAs
    dim3 g2(DIM / B2N, DIM / B2M);           // (8, 16) = 128 CTAs
    for (int s = 0; s < 10; s++) {
        const int c0 = s & 1, n1 = c0 ^ 1;
        // G = X @ X^T (symmetric, triangular + mirror)
        mmagemm_tri<0><<<gtri, 256, SMEM_TRI>>>(
            pXhi[c0], pXlo[c0], pXhi[c0], pXlo[c0],
            nullptr, nullptr, pGhi, pGlo);
        // Bm = c*(G@G) + b*G (symmetric, triangular + mirror)
        mmagemm_tri<1><<<gtri, 256, SMEM_TRI>>>(
            pGhi, pGlo, pGhi, pGlo,
            pGhi, pGlo, pBhi, pBlo);
        // X' = Bm@X + a*X
        if (s < 9) {
            mmagemm_big<0><<<g2, 256, SMEM_BIG>>>(
                pBhi, pBlo, pXThi[c0], pXTlo[c0],
                pXhi[c0], pXlo[c0],
                pXhi[n1], pXlo[n1], pXThi[n1], pXTlo[n1]);
        } else {
            // last step: transposed output straight to single fp16 for final GEMM
            mmagemm_big<1><<<g2, 256, SMEM_BIG>>>(
                pBhi, pBlo, pXThi[c0], pXTlo[c0],
                pXhi[c0], pXlo[c0],
                nullptr, nullptr, pWT, nullptr);
        }
    }
    // out = x16 @ Wfinal^T(fp16) + bias
    dim3 gout(DIM / B2N, B_rows / B2M);  // (8, 128)
    mmagemm_fin<<<gout, 256, SMEM_FIN>>>(px16, pWT, bias, out);
}